// round 5
// baseline (speedup 1.0000x reference)
#include <cuda_runtime.h>
#include <math_constants.h>

#define N_TOK   262144
#define K_CODES 1024
#define D_DIM   64
#define HW      4096
#define CHW     262144
#define Q_ELEMS 16777216
#define GAP_THR 2e-3f
#define FIXCAP  8192

typedef unsigned long long ull;

// ---------------- scratch (device globals; no allocation allowed) ----------------
__device__ float g_Wt[D_DIM * K_CODES];     // transposed weight [d][k]
__device__ float g_wnh[K_CODES];            // 0.5*||w_k||^2
__device__ float g_counts[K_CODES];
__device__ float g_dw[K_CODES * D_DIM];
__device__ float g_neww[K_CODES * D_DIM];
__device__ float g_loss;
__device__ int   g_idx[N_TOK];
__device__ int   g_nfix;
__device__ int4  g_fixlist[FIXCAP];         // {token, c1, c2, pad}

__device__ __forceinline__ ull dup2(float x) {
    unsigned u = __float_as_uint(x);
    ull r;
    asm("mov.b64 %0, {%1, %1};" : "=l"(r) : "r"(u));
    return r;
}
__device__ __forceinline__ void unpack2(ull v, float& lo, float& hi) {
    unsigned a, b;
    asm("mov.b64 {%0, %1}, %2;" : "=r"(a), "=r"(b) : "l"(v));
    lo = __uint_as_float(a); hi = __uint_as_float(b);
}
#define FFMA2(d_, a_, b_, c_) \
    asm("fma.rn.f32x2 %0, %1, %2, %3;" : "=l"(d_) : "l"(a_), "l"(b_), "l"(c_))

// tie-aware "less" : smaller score wins; equal score -> lower index wins
__device__ __forceinline__ bool lt2(float s, int k, float s2, int k2) {
    return (s < s2) || (s == s2 && k < k2);
}

// ---------------- kernel 1: zero accumulators (graph-replay safe) ----------------
__global__ void k_zero() {
    int i = blockIdx.x * blockDim.x + threadIdx.x;
    if (i < K_CODES) g_counts[i] = 0.f;
    if (i < K_CODES * D_DIM) g_dw[i] = 0.f;
    if (i == 0) { g_loss = 0.f; g_nfix = 0; }
}

// ---------------- kernel 2: transpose weight + half-norms ----------------
__global__ void k_prep(const float* __restrict__ w) {
    int k = blockIdx.x * 256 + threadIdx.x;   // 0..1023
    float ss = 0.f;
#pragma unroll
    for (int d = 0; d < 64; d++) {
        float v = w[k * 64 + d];
        g_Wt[d * 1024 + k] = v;               // coalesced writes (lanes vary k)
        ss = fmaf(v, v, ss);
    }
    g_wnh[k] = 0.5f * ss;
}

// ---------------- kernel 3: FFMA2 distances -> idx + scatters + ambiguity list ----
// Block: 128 tokens x full K (8 tiles of 128 codes). 256 threads, 8 tok x 8 codes.
__global__ __launch_bounds__(256)
void k_argmin(const float* __restrict__ in, float* __restrict__ out_idx_f) {
    extern __shared__ float smem[];
    float* A_s  = smem;                      // [64][128] d-major
    float* W_s  = smem + 64 * 128;           // [64][128] d-major
    float* wn_s = smem + 2 * 64 * 128;       // [128]
    int*   idx_s = (int*)(wn_s + 128);       // [128]

    const int tid = threadIdx.x;
    const int ty  = tid >> 4;                // 0..15 : token group (8 tokens)
    const int tx  = tid & 15;                // 0..15 : code group  (8 codes)
    const int token0 = blockIdx.x * 128;
    const int b   = token0 >> 12;
    const int hw0 = token0 & 4095;
    const float* Abase = in + (size_t)b * CHW + hw0;

    // Load A tile [64 d][128 tok] — NCHW layout is already d-major: coalesced.
#pragma unroll
    for (int r = 0; r < 8; r++) {
        int m = r * 256 + tid;               // 0..2047 float4 slots
        int d = m >> 5;
        int c = (m & 31) * 4;
        *(float4*)(A_s + d * 128 + c) = *(const float4*)(Abase + d * HW + c);
    }

    float rb1[8], rb2[8];
    int   ri1[8], ri2[8];
#pragma unroll
    for (int i = 0; i < 8; i++) {
        rb1[i] = CUDART_INF_F; rb2[i] = CUDART_INF_F; ri1[i] = 0; ri2[i] = 0;
    }

    for (int kt = 0; kt < 8; kt++) {
        const int k0 = kt * 128;
        __syncthreads();                     // protect W_s from previous tile readers
#pragma unroll
        for (int r = 0; r < 8; r++) {
            int m = r * 256 + tid;
            int d = m >> 5;
            int c = (m & 31) * 4;
            *(float4*)(W_s + d * 128 + c) = *(const float4*)(g_Wt + d * 1024 + k0 + c);
        }
        if (tid < 32) ((float4*)wn_s)[tid] = ((const float4*)(g_wnh + k0))[tid];
        __syncthreads();

        // acc2[i][jp]: token i  x  code-pair jp (codes 2jp, 2jp+1 in f32x2 lanes)
        ull acc2[8][4];
#pragma unroll
        for (int i = 0; i < 8; i++)
#pragma unroll
            for (int jp = 0; jp < 4; jp++) acc2[i][jp] = 0ull;

#pragma unroll 2
        for (int d = 0; d < 64; d++) {
            float4 a0 = *(const float4*)(A_s + d * 128 + ty * 8);
            float4 a1 = *(const float4*)(A_s + d * 128 + ty * 8 + 4);
            ulonglong2 w01 = *(const ulonglong2*)(W_s + d * 128 + tx * 8);
            ulonglong2 w23 = *(const ulonglong2*)(W_s + d * 128 + tx * 8 + 4);
            ull wp[4] = {w01.x, w01.y, w23.x, w23.y};
            ull ad[8] = {dup2(a0.x), dup2(a0.y), dup2(a0.z), dup2(a0.w),
                         dup2(a1.x), dup2(a1.y), dup2(a1.z), dup2(a1.w)};
#pragma unroll
            for (int i = 0; i < 8; i++)
#pragma unroll
                for (int jp = 0; jp < 4; jp++)
                    FFMA2(acc2[i][jp], ad[i], wp[jp], acc2[i][jp]);
        }

        // top-2 epilogue: score = 0.5||w||^2 - x.w  (monotone in distance)
#pragma unroll
        for (int i = 0; i < 8; i++) {
            float dots[8];
#pragma unroll
            for (int jp = 0; jp < 4; jp++)
                unpack2(acc2[i][jp], dots[2 * jp], dots[2 * jp + 1]);
            float b1 = CUDART_INF_F, b2 = CUDART_INF_F;
            int   i1 = 0, i2 = 0;
#pragma unroll
            for (int j = 0; j < 8; j++) {
                float s = wn_s[tx * 8 + j] - dots[j];
                int   k = k0 + tx * 8 + j;
                if (lt2(s, k, b1, i1)) { b2 = b1; i2 = i1; b1 = s; i1 = k; }
                else if (lt2(s, k, b2, i2)) { b2 = s; i2 = k; }
            }
            // merge sorted pairs across 16 tx lanes (butterfly)
#pragma unroll
            for (int off = 1; off < 16; off <<= 1) {
                float c1 = __shfl_xor_sync(0xffffffffu, b1, off, 16);
                int   j1 = __shfl_xor_sync(0xffffffffu, i1, off, 16);
                float c2 = __shfl_xor_sync(0xffffffffu, b2, off, 16);
                int   j2 = __shfl_xor_sync(0xffffffffu, i2, off, 16);
                if (lt2(c1, j1, b1, i1)) {
                    float tb = b1; int tk = i1;
                    b1 = c1; i1 = j1;
                    if (lt2(c2, j2, tb, tk)) { b2 = c2; i2 = j2; }
                    else                      { b2 = tb; i2 = tk; }
                } else {
                    if (lt2(c1, j1, b2, i2)) { b2 = c1; i2 = j1; }
                }
            }
            // merge tile result into running top-2
            if (lt2(b1, i1, rb1[i], ri1[i])) {
                float tb = rb1[i]; int tk = ri1[i];
                rb1[i] = b1; ri1[i] = i1;
                if (lt2(b2, i2, tb, tk)) { rb2[i] = b2; ri2[i] = i2; }
                else                      { rb2[i] = tb; ri2[i] = tk; }
            } else if (lt2(b1, i1, rb2[i], ri2[i])) {
                rb2[i] = b1; ri2[i] = i1;
            }
        }
    }

    __syncthreads();
    if (tx == 0) {
#pragma unroll
        for (int i = 0; i < 8; i++) {
            int t = token0 + ty * 8 + i;
            idx_s[ty * 8 + i] = ri1[i];
            if (rb2[i] - rb1[i] < GAP_THR) {      // ambiguous: queue fp64 repair
                int pos = atomicAdd(&g_nfix, 1);
                if (pos < FIXCAP) g_fixlist[pos] = make_int4(t, ri1[i], ri2[i], 0);
            }
        }
    }
    __syncthreads();

    if (tid < 128) {
        int k = idx_s[tid];
        atomicAdd(&g_counts[k], 1.0f);
        g_idx[token0 + tid]     = k;
        out_idx_f[token0 + tid] = (float)k;
    }

    // dw scatter: v4 vector reductions, A_s still resident.
#pragma unroll
    for (int it = 0; it < 8; it++) {
        int m = it * 256 + tid;              // 0..2047 = 128 tok x 16 quads
        int t = m & 127;
        int q = m >> 7;
        float a0 = A_s[(q * 4 + 0) * 128 + t];
        float a1 = A_s[(q * 4 + 1) * 128 + t];
        float a2 = A_s[(q * 4 + 2) * 128 + t];
        float a3 = A_s[(q * 4 + 3) * 128 + t];
        float* p = g_dw + idx_s[t] * 64 + q * 4;
        asm volatile("red.global.add.v4.f32 [%0], {%1, %2, %3, %4};"
                     :: "l"(p), "f"(a0), "f"(a1), "f"(a2), "f"(a3) : "memory");
    }
}

// ---------------- kernel 3b: fp64 exact repair of ambiguous tokens ----------------
__global__ __launch_bounds__(128)
void k_fix2(const float* __restrict__ in, const float* __restrict__ w,
            float* __restrict__ out_idx_f) {
    int n = g_nfix; if (n > FIXCAP) n = FIXCAP;
    for (int i = blockIdx.x * blockDim.x + threadIdx.x; i < n;
         i += gridDim.x * blockDim.x) {
        int4 e = g_fixlist[i];
        int t = e.x, c1 = e.y, c2 = e.z;
        const int b  = t >> 12;
        const int hw = t & 4095;
        const float* x  = in + (size_t)b * CHW + hw;
        const float* w1 = w + c1 * 64;
        const float* w2 = w + c2 * 64;
        double d1 = 0.0, d2 = 0.0;
#pragma unroll 8
        for (int d = 0; d < 64; d++) {
            double xv = (double)x[(size_t)d * HW];
            double e1 = xv - (double)w1[d];
            double e2 = xv - (double)w2[d];
            d1 = fma(e1, e1, d1);
            d2 = fma(e2, e2, d2);
        }
        int k = (d2 < d1 || (d2 == d1 && c2 < c1)) ? c2 : c1;
        if (k != c1) {                        // flip: patch idx, counts, dw
            g_idx[t]     = k;
            out_idx_f[t] = (float)k;
            atomicAdd(&g_counts[c1], -1.0f);
            atomicAdd(&g_counts[k],   1.0f);
#pragma unroll 8
            for (int d = 0; d < 64; d++) {
                float xv = x[(size_t)d * HW];
                atomicAdd(&g_dw[c1 * 64 + d], -xv);
                atomicAdd(&g_dw[k  * 64 + d],  xv);
            }
        }
    }
}

// ---------------- kernel 4: EMA update -> new codebook ----------------
__global__ void k_update(const float* __restrict__ ecs, const float* __restrict__ ew) {
    __shared__ float red[1024];
    int k = threadIdx.x;
    float cs = ecs[k] * 0.99f + 0.01f * g_counts[k];
    red[k] = cs;
    __syncthreads();
    for (int s = 512; s > 0; s >>= 1) {
        if (k < s) red[k] += red[k + s];
        __syncthreads();
    }
    float n = red[0];
    float csn = (cs + 1e-5f) / (n + 1024.0f * 1e-5f) * n;   // Laplace smoothing
#pragma unroll 8
    for (int d = 0; d < 64; d++) {
        float e = ew[k * 64 + d] * 0.99f + 0.01f * g_dw[k * 64 + d];
        g_neww[k * 64 + d] = e / csn;
    }
}

// ---------------- kernel 5: gather + straight-through + loss partials ----------------
__global__ __launch_bounds__(256)
void k_gather(const float* __restrict__ in, float* __restrict__ out_q) {
    __shared__ float q_s[128 * 68];          // padded rows (avoid worst bank conflicts)
    __shared__ int   idx_s[128];
    __shared__ float part[8];
    const int tid = threadIdx.x;
    const int token0 = blockIdx.x * 128;
    const int b   = token0 >> 12;
    const int hw0 = token0 & 4095;

    if (tid < 128) idx_s[tid] = g_idx[token0 + tid];
    __syncthreads();

    // stage 128 codebook rows into smem (coalesced float4 gathers from L2-resident table)
#pragma unroll
    for (int r = 0; r < 8; r++) {
        int m  = r * 256 + tid;              // 2048 float4
        int t  = m >> 4;
        int sg = (m & 15) * 4;
        float4 v = *(const float4*)(g_neww + idx_s[t] * 64 + sg);
        *(float4*)(q_s + t * 68 + sg) = v;
    }
    __syncthreads();

    const size_t base = (size_t)b * CHW + hw0;
    float lsum = 0.f;
#pragma unroll 4
    for (int it = 0; it < 32; it++) {
        int d = it * 2 + (tid >> 7);
        int t = tid & 127;
        size_t g = base + (size_t)d * HW + t;
        float x  = in[g];
        float q  = q_s[t * 68 + d];
        float dt = q - x;                    // matches reference rounding order
        out_q[g] = x + dt;                   // straight-through: x + (q - x)
        lsum = fmaf(dt, dt, lsum);
    }
#pragma unroll
    for (int off = 16; off > 0; off >>= 1)
        lsum += __shfl_xor_sync(0xffffffffu, lsum, off);
    if ((tid & 31) == 0) part[tid >> 5] = lsum;
    __syncthreads();
    if (tid == 0) {
        float s = 0.f;
#pragma unroll
        for (int i = 0; i < 8; i++) s += part[i];
        atomicAdd(&g_loss, s);
    }
}

// ---------------- kernel 6: finalize loss ----------------
__global__ void k_final(float* out) {
    out[0] = 0.25f * (g_loss * (1.0f / 16777216.0f));
}

// ---------------- launch ----------------
extern "C" void kernel_launch(void* const* d_in, const int* in_sizes, int n_in,
                              void* d_out, int out_size) {
    const float* in  = (const float*)d_in[0];   // (64,64,64,64) NCHW
    const float* w   = (const float*)d_in[1];   // (1024,64)
    const float* ecs = (const float*)d_in[2];   // (1024,)
    const float* ew  = (const float*)d_in[3];   // (1024,64)
    float* out      = (float*)d_out;            // [loss | quantized NCHW | idx]
    float* out_q    = out + 1;
    float* out_idx  = out + 1 + Q_ELEMS;

    const int ARG_SMEM = (2 * 64 * 128 + 128) * 4 + 128 * 4;  // 66560 B

    k_zero<<<(K_CODES * D_DIM + 255) / 256, 256>>>();
    k_prep<<<4, 256>>>(w);
    cudaFuncSetAttribute(k_argmin, cudaFuncAttributeMaxDynamicSharedMemorySize, ARG_SMEM);
    k_argmin<<<N_TOK / 128, 256, ARG_SMEM>>>(in, out_idx);
    k_fix2<<<32, 128>>>(in, w, out_idx);
    k_update<<<1, 1024>>>(ecs, ew);
    k_gather<<<N_TOK / 128, 256>>>(in, out_q);
    k_final<<<1, 1>>>(out);
}

// round 6
// speedup vs baseline: 1.2935x; 1.2935x over previous
#include <cuda_runtime.h>
#include <math_constants.h>

#define N_TOK   262144
#define K_CODES 1024
#define D_DIM   64
#define HW      4096
#define CHW     262144
#define Q_ELEMS 16777216
#define GAP_T   1e-2f          // score-unit flag threshold (>= 2*eps bound, ~6x margin)
#define FIXCAP  32768

// ---------------- scratch (device globals; no allocation allowed) ----------------
__device__ uint4 g_Wpack[8 * 16 * 4 * 32];   // fragment-packed codebook {bh0,bh1,bl0,bl1}
__device__ float g_wnh[K_CODES];             // 0.5*||w_k||^2
__device__ float g_counts[K_CODES];
__device__ float g_dw[K_CODES * D_DIM];
__device__ float g_neww[K_CODES * D_DIM];
__device__ float g_loss;
__device__ int   g_idx[N_TOK];
__device__ int   g_nfix;
__device__ int   g_fixlist[FIXCAP];

// ---------------- helpers ----------------
__device__ __forceinline__ unsigned pk_bf16x2(float hi, float lo) {
    unsigned r;
    asm("cvt.rn.bf16x2.f32 %0, %1, %2;" : "=r"(r) : "f"(hi), "f"(lo));
    return r;
}
__device__ __forceinline__ float bf_lo(unsigned p) { return __uint_as_float(p << 16); }
__device__ __forceinline__ float bf_hi(unsigned p) { return __uint_as_float(p & 0xffff0000u); }

__device__ __forceinline__ void mma16816(float* c, const unsigned* a,
                                         unsigned b0, unsigned b1) {
    asm("mma.sync.aligned.m16n8k16.row.col.f32.bf16.bf16.f32 "
        "{%0,%1,%2,%3}, {%4,%5,%6,%7}, {%8,%9}, {%0,%1,%2,%3};"
        : "+f"(c[0]), "+f"(c[1]), "+f"(c[2]), "+f"(c[3])
        : "r"(a[0]), "r"(a[1]), "r"(a[2]), "r"(a[3]), "r"(b0), "r"(b1));
}

// tie-aware "less": smaller score wins; equal -> lower index
__device__ __forceinline__ bool lt2(float s, int k, float s2, int k2) {
    return (s < s2) || (s == s2 && k < k2);
}

// ---------------- kernel 1: zero accumulators ----------------
__global__ void k_zero() {
    int i = blockIdx.x * blockDim.x + threadIdx.x;
    if (i < K_CODES) g_counts[i] = 0.f;
    if (i < K_CODES * D_DIM) g_dw[i] = 0.f;
    if (i == 0) { g_loss = 0.f; g_nfix = 0; }
}

// ---------------- kernel 2a: half-norms ----------------
__global__ void k_prep(const float* __restrict__ w) {
    int k = blockIdx.x * 256 + threadIdx.x;   // 0..1023
    float ss = 0.f;
#pragma unroll
    for (int d = 0; d < 64; d++) {
        float v = w[k * 64 + d];
        ss = fmaf(v, v, ss);
    }
    g_wnh[k] = 0.5f * ss;
}

// ---------------- kernel 2b: pack codebook into mma B-fragment order ----------------
// item -> (kt, nt, kst, lane); stores {bh0, bh1, bl0, bl1} for m16n8k16 col-major B.
__global__ void k_pack(const float* __restrict__ w) {
    int item = blockIdx.x * 256 + threadIdx.x;    // 0..16383
    int lane = item & 31;
    int kst  = (item >> 5) & 3;
    int nt   = (item >> 7) & 15;
    int kt   = item >> 11;
    int n = kt * 128 + nt * 8 + (lane >> 2);
    int k = kst * 16 + 2 * (lane & 3);
    const float* wr = w + n * 64;
    float x0 = wr[k],     x1 = wr[k + 1];
    float x2 = wr[k + 8], x3 = wr[k + 9];
    unsigned h0 = pk_bf16x2(x1, x0);
    unsigned h1 = pk_bf16x2(x3, x2);
    unsigned l0 = pk_bf16x2(x1 - bf_hi(h0), x0 - bf_lo(h0));
    unsigned l1 = pk_bf16x2(x3 - bf_hi(h1), x2 - bf_lo(h1));
    g_Wpack[item] = make_uint4(h0, h1, l0, l1);
}

// ---------------- kernel 3: tensor-core distances + top-2 + scatters + flags ------
// Block: 256 threads = 8 warps, 256 tokens. Warp: 32 tokens (2 m-tiles of 16).
// K loop: 8 code-tiles of 128; per tile 16 n-tiles; 3 bf16-split MMAs per kst.
__global__ __launch_bounds__(256)
void k_argmin(const float* __restrict__ in, float* __restrict__ out_idx_f) {
    extern __shared__ char smem[];
    float* A_s   = (float*)smem;                       // [64][256] d-major (64 KB)
    uint4* Wt4   = (uint4*)(smem + 65536);             // 2048 uint4 (32 KB)
    float* wn_s  = (float*)(smem + 65536 + 32768);     // [128]
    int*   idx_s = (int*)(smem + 65536 + 32768 + 512); // [256]

    const int tid  = threadIdx.x;
    const int warp = tid >> 5;
    const int lane = tid & 31;
    const int g    = lane >> 2;        // 0..7
    const int t    = lane & 3;         // 0..3
    const int token0 = blockIdx.x * 256;
    const int b   = token0 >> 12;
    const int hw0 = token0 & 4095;
    const float* Abase = in + (size_t)b * CHW + hw0;

    // Load A tile [64 d][256 tok] — coalesced (NCHW is d-major).
#pragma unroll
    for (int r = 0; r < 16; r++) {
        int m = r * 256 + tid;         // 0..4095 float4 slots
        int d = m >> 6;
        int c = (m & 63) * 4;
        *(float4*)(A_s + d * 256 + c) = *(const float4*)(Abase + (size_t)d * HW + c);
    }
    __syncthreads();

    // Build resident A fragments (hi/lo bf16x2), 2 m-tiles x 4 k-steps x 4 regs.
    unsigned Ah[2][4][4], Al[2][4][4];
#pragma unroll
    for (int mt = 0; mt < 2; mt++) {
        int r0 = warp * 32 + mt * 16 + g;
        int r1 = r0 + 8;
#pragma unroll
        for (int kst = 0; kst < 4; kst++) {
            int kb = kst * 16;
#pragma unroll
            for (int f = 0; f < 4; f++) {
                int row = (f & 1) ? r1 : r0;
                int kk  = kb + 2 * t + ((f >> 1) ? 8 : 0);
                float xa = A_s[kk * 256 + row];
                float xb = A_s[(kk + 1) * 256 + row];
                unsigned h = pk_bf16x2(xb, xa);
                Ah[mt][kst][f] = h;
                Al[mt][kst][f] = pk_bf16x2(xb - bf_hi(h), xa - bf_lo(h));
            }
        }
    }

    // Running per-thread top-2 for 4 token rows: rr = mt*2 + (0: row g, 1: row g+8)
    float rs1[4], rs2[4];
    int   rk1[4], rk2[4];
#pragma unroll
    for (int i = 0; i < 4; i++) { rs1[i] = CUDART_INF_F; rs2[i] = CUDART_INF_F; rk1[i] = 0; rk2[i] = 0; }

    for (int kt = 0; kt < 8; kt++) {
        __syncthreads();
        // cooperative load of packed W tile (2048 uint4) + norms (128 f)
#pragma unroll
        for (int r = 0; r < 8; r++)
            Wt4[r * 256 + tid] = g_Wpack[kt * 2048 + r * 256 + tid];
        if (tid < 32) ((float4*)wn_s)[tid] = ((const float4*)(g_wnh + kt * 128))[tid];
        __syncthreads();

        for (int nt = 0; nt < 16; nt++) {
            float c0[4] = {0.f, 0.f, 0.f, 0.f};
            float c1[4] = {0.f, 0.f, 0.f, 0.f};
#pragma unroll
            for (int kst = 0; kst < 4; kst++) {
                uint4 bp = Wt4[(nt * 4 + kst) * 32 + lane];
                mma16816(c0, Ah[0][kst], bp.x, bp.y);   // ah*bh
                mma16816(c0, Al[0][kst], bp.x, bp.y);   // al*bh
                mma16816(c0, Ah[0][kst], bp.z, bp.w);   // ah*bl
                mma16816(c1, Ah[1][kst], bp.x, bp.y);
                mma16816(c1, Al[1][kst], bp.x, bp.y);
                mma16816(c1, Ah[1][kst], bp.z, bp.w);
            }
            // epilogue: scores for 4 rows x 2 cols; update running top-2
            int   n0 = kt * 128 + nt * 8;
            float wa = wn_s[nt * 8 + 2 * t];
            float wb = wn_s[nt * 8 + 2 * t + 1];
            int   ka = n0 + 2 * t, kb = ka + 1;
#pragma unroll
            for (int rr = 0; rr < 4; rr++) {
                const float* cc = (rr < 2) ? c0 : c1;
                float da = cc[(rr & 1) ? 2 : 0];
                float db = cc[(rr & 1) ? 3 : 1];
                float sa = wa - da;
                float sb = wb - db;
                if (lt2(sa, ka, rs1[rr], rk1[rr])) {
                    rs2[rr] = rs1[rr]; rk2[rr] = rk1[rr]; rs1[rr] = sa; rk1[rr] = ka;
                } else if (lt2(sa, ka, rs2[rr], rk2[rr])) { rs2[rr] = sa; rk2[rr] = ka; }
                if (lt2(sb, kb, rs1[rr], rk1[rr])) {
                    rs2[rr] = rs1[rr]; rk2[rr] = rk1[rr]; rs1[rr] = sb; rk1[rr] = kb;
                } else if (lt2(sb, kb, rs2[rr], rk2[rr])) { rs2[rr] = sb; rk2[rr] = kb; }
            }
        }
    }

    // merge top-2 across the 4-lane column group (butterfly, width 4)
#pragma unroll
    for (int rr = 0; rr < 4; rr++) {
#pragma unroll
        for (int off = 1; off <= 2; off <<= 1) {
            float c1v = __shfl_xor_sync(0xffffffffu, rs1[rr], off, 4);
            int   j1  = __shfl_xor_sync(0xffffffffu, rk1[rr], off, 4);
            float c2v = __shfl_xor_sync(0xffffffffu, rs2[rr], off, 4);
            int   j2  = __shfl_xor_sync(0xffffffffu, rk2[rr], off, 4);
            if (lt2(c1v, j1, rs1[rr], rk1[rr])) {
                float tb = rs1[rr]; int tk = rk1[rr];
                rs1[rr] = c1v; rk1[rr] = j1;
                if (lt2(c2v, j2, tb, tk)) { rs2[rr] = c2v; rk2[rr] = j2; }
                else                       { rs2[rr] = tb;  rk2[rr] = tk; }
            } else if (lt2(c1v, j1, rs2[rr], rk2[rr])) { rs2[rr] = c1v; rk2[rr] = j1; }
        }
    }
    __syncthreads();
    if (t == 0) {
#pragma unroll
        for (int rr = 0; rr < 4; rr++) {
            int L = warp * 32 + (rr >> 1) * 16 + (rr & 1) * 8 + g;
            idx_s[L] = rk1[rr];
            if (rs2[rr] - rs1[rr] < GAP_T) {      // ambiguous under bf16x2 noise
                int pos = atomicAdd(&g_nfix, 1);
                if (pos < FIXCAP) g_fixlist[pos] = token0 + L;
            }
        }
    }
    __syncthreads();

    // idx + counts (256 tokens, one per thread)
    {
        int k = idx_s[tid];
        atomicAdd(&g_counts[k], 1.0f);
        g_idx[token0 + tid]     = k;
        out_idx_f[token0 + tid] = (float)k;
    }

    // dw scatter: v4 vector reductions; A_s still resident.
#pragma unroll
    for (int it = 0; it < 16; it++) {
        int m   = it * 256 + tid;       // 0..4095 = 256 tok x 16 quads
        int tkn = m & 255;
        int q   = m >> 8;
        float a0 = A_s[(q * 4 + 0) * 256 + tkn];
        float a1 = A_s[(q * 4 + 1) * 256 + tkn];
        float a2 = A_s[(q * 4 + 2) * 256 + tkn];
        float a3 = A_s[(q * 4 + 3) * 256 + tkn];
        float* p = g_dw + idx_s[tkn] * 64 + q * 4;
        asm volatile("red.global.add.v4.f32 [%0], {%1, %2, %3, %4};"
                     :: "l"(p), "f"(a0), "f"(a1), "f"(a2), "f"(a3) : "memory");
    }
}

// ---------------- kernel 3b: fp64 full-scan repair of flagged tokens --------------
__global__ __launch_bounds__(256)
void k_fix3(const float* __restrict__ in, const float* __restrict__ w,
            float* __restrict__ out_idx_f) {
    __shared__ float xs[8][64];
    int n = g_nfix; if (n > FIXCAP) n = FIXCAP;
    const int warp = threadIdx.x >> 5;
    const int lane = threadIdx.x & 31;
    for (int i = blockIdx.x * 8 + warp; i < n; i += gridDim.x * 8) {
        int t = g_fixlist[i];
        const float* x = in + (size_t)(t >> 12) * CHW + (t & 4095);
        xs[warp][lane]      = x[(size_t)lane * HW];
        xs[warp][lane + 32] = x[(size_t)(lane + 32) * HW];
        __syncwarp();

        double bd = CUDART_INF;
        int    bk = 0x7fffffff;
        // 4 concurrent accumulation chains for DFMA latency hiding
        for (int jj = 0; jj < 8; jj++) {
            int    c[4];
            double acc[4] = {0.0, 0.0, 0.0, 0.0};
#pragma unroll
            for (int u = 0; u < 4; u++) c[u] = (jj + u * 8) * 32 + lane;
#pragma unroll 4
            for (int q = 0; q < 16; q++) {
                float4 wv[4];
#pragma unroll
                for (int u = 0; u < 4; u++)
                    wv[u] = ((const float4*)(w + c[u] * 64))[q];
#pragma unroll
                for (int r = 0; r < 4; r++) {
                    double xv = (double)xs[warp][q * 4 + r];
#pragma unroll
                    for (int u = 0; u < 4; u++) {
                        double e = xv - (double)((&wv[u].x)[r]);
                        acc[u] = fma(e, e, acc[u]);
                    }
                }
            }
#pragma unroll
            for (int u = 0; u < 4; u++)
                if (acc[u] < bd || (acc[u] == bd && c[u] < bk)) { bd = acc[u]; bk = c[u]; }
        }
        // warp-reduce exact argmin
#pragma unroll
        for (int off = 16; off > 0; off >>= 1) {
            double od = __shfl_xor_sync(0xffffffffu, bd, off);
            int    ok = __shfl_xor_sync(0xffffffffu, bk, off);
            if (od < bd || (od == bd && ok < bk)) { bd = od; bk = ok; }
        }
        if (lane == 0) {
            int old = g_idx[t];
            if (bk != old) {
                g_idx[t]     = bk;
                out_idx_f[t] = (float)bk;
                atomicAdd(&g_counts[old], -1.0f);
                atomicAdd(&g_counts[bk],   1.0f);
                for (int d = 0; d < 64; d++) {
                    float xv = xs[warp][d];
                    atomicAdd(&g_dw[old * 64 + d], -xv);
                    atomicAdd(&g_dw[bk  * 64 + d],  xv);
                }
            }
        }
        __syncwarp();
    }
}

// ---------------- kernel 4: EMA update -> new codebook ----------------
__global__ void k_update(const float* __restrict__ ecs, const float* __restrict__ ew) {
    __shared__ float red[1024];
    int k = threadIdx.x;
    float cs = ecs[k] * 0.99f + 0.01f * g_counts[k];
    red[k] = cs;
    __syncthreads();
    for (int s = 512; s > 0; s >>= 1) {
        if (k < s) red[k] += red[k + s];
        __syncthreads();
    }
    float n = red[0];
    float csn = (cs + 1e-5f) / (n + 1024.0f * 1e-5f) * n;   // Laplace smoothing
#pragma unroll 8
    for (int d = 0; d < 64; d++) {
        float e = ew[k * 64 + d] * 0.99f + 0.01f * g_dw[k * 64 + d];
        g_neww[k * 64 + d] = e / csn;
    }
}

// ---------------- kernel 5: gather + straight-through + loss partials -------------
__global__ __launch_bounds__(256)
void k_gather(const float* __restrict__ in, float* __restrict__ out_q) {
    __shared__ float q_s[128 * 68];
    __shared__ int   idx_s[128];
    __shared__ float part[8];
    const int tid = threadIdx.x;
    const int token0 = blockIdx.x * 128;
    const int b   = token0 >> 12;
    const int hw0 = token0 & 4095;

    if (tid < 128) idx_s[tid] = g_idx[token0 + tid];
    __syncthreads();

#pragma unroll
    for (int r = 0; r < 8; r++) {
        int m  = r * 256 + tid;
        int t  = m >> 4;
        int sg = (m & 15) * 4;
        float4 v = *(const float4*)(g_neww + idx_s[t] * 64 + sg);
        *(float4*)(q_s + t * 68 + sg) = v;
    }
    __syncthreads();

    const size_t base = (size_t)b * CHW + hw0;
    float lsum = 0.f;
#pragma unroll 4
    for (int it = 0; it < 32; it++) {
        int d = it * 2 + (tid >> 7);
        int t = tid & 127;
        size_t gidx = base + (size_t)d * HW + t;
        float x  = in[gidx];
        float q  = q_s[t * 68 + d];
        float dt = q - x;
        out_q[gidx] = x + dt;
        lsum = fmaf(dt, dt, lsum);
    }
#pragma unroll
    for (int off = 16; off > 0; off >>= 1)
        lsum += __shfl_xor_sync(0xffffffffu, lsum, off);
    if ((tid & 31) == 0) part[tid >> 5] = lsum;
    __syncthreads();
    if (tid == 0) {
        float s = 0.f;
#pragma unroll
        for (int i = 0; i < 8; i++) s += part[i];
        atomicAdd(&g_loss, s);
    }
}

// ---------------- kernel 6: finalize loss ----------------
__global__ void k_final(float* out) {
    out[0] = 0.25f * (g_loss * (1.0f / 16777216.0f));
}

// ---------------- launch ----------------
extern "C" void kernel_launch(void* const* d_in, const int* in_sizes, int n_in,
                              void* d_out, int out_size) {
    const float* in  = (const float*)d_in[0];   // (64,64,64,64) NCHW
    const float* w   = (const float*)d_in[1];   // (1024,64)
    const float* ecs = (const float*)d_in[2];   // (1024,)
    const float* ew  = (const float*)d_in[3];   // (1024,64)
    float* out      = (float*)d_out;            // [loss | quantized NCHW | idx]
    float* out_q    = out + 1;
    float* out_idx  = out + 1 + Q_ELEMS;

    const int ARG_SMEM = 65536 + 32768 + 512 + 1024;   // 99840 B

    k_zero<<<(K_CODES * D_DIM + 255) / 256, 256>>>();
    k_prep<<<4, 256>>>(w);
    k_pack<<<64, 256>>>(w);
    cudaFuncSetAttribute(k_argmin, cudaFuncAttributeMaxDynamicSharedMemorySize, ARG_SMEM);
    k_argmin<<<N_TOK / 256, 256, ARG_SMEM>>>(in, out_idx);
    k_fix3<<<148, 256>>>(in, w, out_idx);
    k_update<<<1, 1024>>>(ecs, ew);
    k_gather<<<N_TOK / 128, 256>>>(in, out_q);
    k_final<<<1, 1>>>(out);
}

// round 7
// speedup vs baseline: 1.6245x; 1.2559x over previous
#include <cuda_runtime.h>
#include <cuda_fp16.h>
#include <math_constants.h>

#define N_TOK   262144
#define K_CODES 1024
#define D_DIM   64
#define HW      4096
#define CHW     262144
#define Q_ELEMS 16777216
#define GAP_T   5e-4f          // fp16-split eps ~1e-5 -> 50x margin
#define FIXCAP  32768

// ---------------- scratch (device globals; no allocation allowed) ----------------
__device__ uint4 g_Wpack[8 * 16 * 4 * 32];   // fragment-packed codebook {bh0,bh1,bl0,bl1}
__device__ float g_wnh[K_CODES];             // 0.5*||w_k||^2
__device__ float g_counts[K_CODES];
__device__ float g_dw[K_CODES * D_DIM];
__device__ float g_neww[K_CODES * D_DIM];
__device__ float g_loss;
__device__ int   g_idx[N_TOK];
__device__ int   g_nfix;
__device__ int   g_fixlist[FIXCAP];

// ---------------- helpers ----------------
// pack (a -> lo half, b -> hi half) as f16x2, and residual pair
__device__ __forceinline__ unsigned h2_bits(__half2 h) {
    return *reinterpret_cast<unsigned*>(&h);
}
__device__ __forceinline__ void split_pair(float xa, float xb,
                                           unsigned& hi, unsigned& lo) {
    __half2 h = __floats2half2_rn(xa, xb);
    float2 hf = __half22float2(h);
    __half2 l = __floats2half2_rn(xa - hf.x, xb - hf.y);
    hi = h2_bits(h);
    lo = h2_bits(l);
}

__device__ __forceinline__ void mma16816(float* c, const unsigned* a,
                                         unsigned b0, unsigned b1) {
    asm("mma.sync.aligned.m16n8k16.row.col.f32.f16.f16.f32 "
        "{%0,%1,%2,%3}, {%4,%5,%6,%7}, {%8,%9}, {%0,%1,%2,%3};"
        : "+f"(c[0]), "+f"(c[1]), "+f"(c[2]), "+f"(c[3])
        : "r"(a[0]), "r"(a[1]), "r"(a[2]), "r"(a[3]), "r"(b0), "r"(b1));
}

// ---------------- kernel 1: zero accumulators ----------------
__global__ void k_zero() {
    int i = blockIdx.x * blockDim.x + threadIdx.x;
    if (i < K_CODES) g_counts[i] = 0.f;
    if (i < K_CODES * D_DIM) g_dw[i] = 0.f;
    if (i == 0) { g_loss = 0.f; g_nfix = 0; }
}

// ---------------- kernel 2a: half-norms ----------------
__global__ void k_prep(const float* __restrict__ w) {
    int k = blockIdx.x * 256 + threadIdx.x;   // 0..1023
    float ss = 0.f;
#pragma unroll
    for (int d = 0; d < 64; d++) {
        float v = w[k * 64 + d];
        ss = fmaf(v, v, ss);
    }
    g_wnh[k] = 0.5f * ss;
}

// ---------------- kernel 2b: pack codebook into mma B-fragment order --------------
// item -> (kt, nt, kst, lane); stores {bh0, bh1, bl0, bl1} for m16n8k16 col-major B.
__global__ void k_pack(const float* __restrict__ w) {
    int item = blockIdx.x * 256 + threadIdx.x;    // 0..16383
    int lane = item & 31;
    int kst  = (item >> 5) & 3;
    int nt   = (item >> 7) & 15;
    int kt   = item >> 11;
    int n = kt * 128 + nt * 8 + (lane >> 2);
    int k = kst * 16 + 2 * (lane & 3);
    const float* wr = w + n * 64;
    unsigned h0, l0, h1, l1;
    split_pair(wr[k],     wr[k + 1], h0, l0);
    split_pair(wr[k + 8], wr[k + 9], h1, l1);
    g_Wpack[item] = make_uint4(h0, h1, l0, l1);
}

// ---------------- kernel 3: tensor-core distances + top-2 + scatters + flags ------
// Block: 256 threads = 8 warps, 256 tokens. Warp: 32 tokens (2 m-tiles of 16).
__global__ __launch_bounds__(256)
void k_argmin(const float* __restrict__ in, float* __restrict__ out_idx_f) {
    extern __shared__ char smem[];
    float* A_s   = (float*)smem;                       // [64][256] d-major (64 KB)
    uint4* Wt4   = (uint4*)(smem + 65536);             // 2048 uint4 (32 KB)
    float* wn_s  = (float*)(smem + 65536 + 32768);     // [128]
    int*   idx_s = (int*)(smem + 65536 + 32768 + 512); // [256]

    const int tid  = threadIdx.x;
    const int warp = tid >> 5;
    const int lane = tid & 31;
    const int g    = lane >> 2;        // 0..7
    const int t    = lane & 3;         // 0..3
    const int token0 = blockIdx.x * 256;
    const int b   = token0 >> 12;
    const int hw0 = token0 & 4095;
    const float* Abase = in + (size_t)b * CHW + hw0;

    // Load A tile [64 d][256 tok] — coalesced (NCHW is d-major).
#pragma unroll
    for (int r = 0; r < 16; r++) {
        int m = r * 256 + tid;         // 0..4095 float4 slots
        int d = m >> 6;
        int c = (m & 63) * 4;
        *(float4*)(A_s + d * 256 + c) = *(const float4*)(Abase + (size_t)d * HW + c);
    }
    __syncthreads();

    // Resident A fragments (hi/lo f16x2): 2 m-tiles x 4 k-steps x 4 regs.
    unsigned Ah[2][4][4], Al[2][4][4];
#pragma unroll
    for (int mt = 0; mt < 2; mt++) {
        int r0 = warp * 32 + mt * 16 + g;
        int r1 = r0 + 8;
#pragma unroll
        for (int kst = 0; kst < 4; kst++) {
            int kb = kst * 16;
#pragma unroll
            for (int f = 0; f < 4; f++) {
                int row = (f & 1) ? r1 : r0;
                int kk  = kb + 2 * t + ((f >> 1) ? 8 : 0);
                split_pair(A_s[kk * 256 + row], A_s[(kk + 1) * 256 + row],
                           Ah[mt][kst][f], Al[mt][kst][f]);
            }
        }
    }

    // Running per-thread min (with index) + second-min score for 4 token rows.
    float rs1[4], rs2[4];
    int   rk1[4];
#pragma unroll
    for (int i = 0; i < 4; i++) { rs1[i] = CUDART_INF_F; rs2[i] = CUDART_INF_F; rk1[i] = 0; }

    for (int kt = 0; kt < 8; kt++) {
        __syncthreads();
#pragma unroll
        for (int r = 0; r < 8; r++)
            Wt4[r * 256 + tid] = g_Wpack[kt * 2048 + r * 256 + tid];
        if (tid < 32) ((float4*)wn_s)[tid] = ((const float4*)(g_wnh + kt * 128))[tid];
        __syncthreads();

        for (int nt = 0; nt < 16; nt++) {
            float c0[4] = {0.f, 0.f, 0.f, 0.f};
            float c1[4] = {0.f, 0.f, 0.f, 0.f};
#pragma unroll
            for (int kst = 0; kst < 4; kst++) {
                uint4 bp = Wt4[(nt * 4 + kst) * 32 + lane];
                mma16816(c0, Ah[0][kst], bp.x, bp.y);   // ah*bh
                mma16816(c0, Al[0][kst], bp.x, bp.y);   // al*bh
                mma16816(c0, Ah[0][kst], bp.z, bp.w);   // ah*bl
                mma16816(c1, Ah[1][kst], bp.x, bp.y);
                mma16816(c1, Al[1][kst], bp.x, bp.y);
                mma16816(c1, Ah[1][kst], bp.z, bp.w);
            }
            // epilogue: score = 0.5||w||^2 - x.w ; score-only top-2 + argmin index
            float wa = wn_s[nt * 8 + 2 * t];
            float wb = wn_s[nt * 8 + 2 * t + 1];
            int   ka = kt * 128 + nt * 8 + 2 * t;
#pragma unroll
            for (int rr = 0; rr < 4; rr++) {
                const float* cc = (rr < 2) ? c0 : c1;
                float sa = wa - cc[(rr & 1) ? 2 : 0];
                float sb = wb - cc[(rr & 1) ? 3 : 1];
                bool pa = sa < rs1[rr];
                rs2[rr] = fminf(rs2[rr], fmaxf(rs1[rr], sa));
                rs1[rr] = fminf(rs1[rr], sa);
                rk1[rr] = pa ? ka : rk1[rr];
                bool pb = sb < rs1[rr];
                rs2[rr] = fminf(rs2[rr], fmaxf(rs1[rr], sb));
                rs1[rr] = fminf(rs1[rr], sb);
                rk1[rr] = pb ? (ka + 1) : rk1[rr];
            }
        }
    }

    // merge across the 4-lane column group (butterfly, width 4)
#pragma unroll
    for (int rr = 0; rr < 4; rr++) {
#pragma unroll
        for (int off = 1; off <= 2; off <<= 1) {
            float o1 = __shfl_xor_sync(0xffffffffu, rs1[rr], off, 4);
            int   ok = __shfl_xor_sync(0xffffffffu, rk1[rr], off, 4);
            float o2 = __shfl_xor_sync(0xffffffffu, rs2[rr], off, 4);
            float n1 = fminf(rs1[rr], o1);
            float n2 = fminf(fmaxf(rs1[rr], o1), fminf(rs2[rr], o2));
            rk1[rr] = (o1 < rs1[rr] || (o1 == rs1[rr] && ok < rk1[rr])) ? ok : rk1[rr];
            rs1[rr] = n1; rs2[rr] = n2;
        }
    }
    __syncthreads();
    if (t == 0) {
#pragma unroll
        for (int rr = 0; rr < 4; rr++) {
            int L = warp * 32 + (rr >> 1) * 16 + (rr & 1) * 8 + g;
            idx_s[L] = rk1[rr];
            if (rs2[rr] - rs1[rr] < GAP_T) {      // ambiguous under fp16-split noise
                int pos = atomicAdd(&g_nfix, 1);
                if (pos < FIXCAP) g_fixlist[pos] = token0 + L;
            }
        }
    }
    __syncthreads();

    // idx + counts (256 tokens, one per thread)
    {
        int k = idx_s[tid];
        atomicAdd(&g_counts[k], 1.0f);
        g_idx[token0 + tid]     = k;
        out_idx_f[token0 + tid] = (float)k;
    }

    // dw scatter: v4 vector reductions; A_s still resident.
#pragma unroll
    for (int it = 0; it < 16; it++) {
        int m   = it * 256 + tid;       // 0..4095 = 256 tok x 16 quads
        int tkn = m & 255;
        int q   = m >> 8;
        float a0 = A_s[(q * 4 + 0) * 256 + tkn];
        float a1 = A_s[(q * 4 + 1) * 256 + tkn];
        float a2 = A_s[(q * 4 + 2) * 256 + tkn];
        float a3 = A_s[(q * 4 + 3) * 256 + tkn];
        float* p = g_dw + idx_s[tkn] * 64 + q * 4;
        asm volatile("red.global.add.v4.f32 [%0], {%1, %2, %3, %4};"
                     :: "l"(p), "f"(a0), "f"(a1), "f"(a2), "f"(a3) : "memory");
    }
}

// ---------------- kernel 3b: fp64 full-scan repair of flagged tokens --------------
__global__ __launch_bounds__(256)
void k_fix3(const float* __restrict__ in, const float* __restrict__ w,
            float* __restrict__ out_idx_f) {
    __shared__ float xs[8][64];
    int n = g_nfix; if (n > FIXCAP) n = FIXCAP;
    const int warp = threadIdx.x >> 5;
    const int lane = threadIdx.x & 31;
    for (int i = blockIdx.x * 8 + warp; i < n; i += gridDim.x * 8) {
        int t = g_fixlist[i];
        const float* x = in + (size_t)(t >> 12) * CHW + (t & 4095);
        xs[warp][lane]      = x[(size_t)lane * HW];
        xs[warp][lane + 32] = x[(size_t)(lane + 32) * HW];
        __syncwarp();

        double bd = CUDART_INF;
        int    bk = 0x7fffffff;
        for (int jj = 0; jj < 8; jj++) {
            int    c[4];
            double acc[4] = {0.0, 0.0, 0.0, 0.0};
#pragma unroll
            for (int u = 0; u < 4; u++) c[u] = (jj + u * 8) * 32 + lane;
#pragma unroll 4
            for (int q = 0; q < 16; q++) {
                float4 wv[4];
#pragma unroll
                for (int u = 0; u < 4; u++)
                    wv[u] = ((const float4*)(w + c[u] * 64))[q];
#pragma unroll
                for (int r = 0; r < 4; r++) {
                    double xv = (double)xs[warp][q * 4 + r];
#pragma unroll
                    for (int u = 0; u < 4; u++) {
                        double e = xv - (double)((&wv[u].x)[r]);
                        acc[u] = fma(e, e, acc[u]);
                    }
                }
            }
#pragma unroll
            for (int u = 0; u < 4; u++)
                if (acc[u] < bd || (acc[u] == bd && c[u] < bk)) { bd = acc[u]; bk = c[u]; }
        }
#pragma unroll
        for (int off = 16; off > 0; off >>= 1) {
            double od = __shfl_xor_sync(0xffffffffu, bd, off);
            int    ok = __shfl_xor_sync(0xffffffffu, bk, off);
            if (od < bd || (od == bd && ok < bk)) { bd = od; bk = ok; }
        }
        if (lane == 0) {
            int old = g_idx[t];
            if (bk != old) {
                g_idx[t]     = bk;
                out_idx_f[t] = (float)bk;
                atomicAdd(&g_counts[old], -1.0f);
                atomicAdd(&g_counts[bk],   1.0f);
                for (int d = 0; d < 64; d++) {
                    float xv = xs[warp][d];
                    atomicAdd(&g_dw[old * 64 + d], -xv);
                    atomicAdd(&g_dw[bk  * 64 + d],  xv);
                }
            }
        }
        __syncwarp();
    }
}

// ---------------- kernel 4: EMA update -> new codebook ----------------
__global__ void k_update(const float* __restrict__ ecs, const float* __restrict__ ew) {
    __shared__ float red[1024];
    int k = threadIdx.x;
    float cs = ecs[k] * 0.99f + 0.01f * g_counts[k];
    red[k] = cs;
    __syncthreads();
    for (int s = 512; s > 0; s >>= 1) {
        if (k < s) red[k] += red[k + s];
        __syncthreads();
    }
    float n = red[0];
    float csn = (cs + 1e-5f) / (n + 1024.0f * 1e-5f) * n;   // Laplace smoothing
#pragma unroll 8
    for (int d = 0; d < 64; d++) {
        float e = ew[k * 64 + d] * 0.99f + 0.01f * g_dw[k * 64 + d];
        g_neww[k * 64 + d] = e / csn;
    }
}

// ---------------- kernel 5: gather + straight-through + loss partials -------------
__global__ __launch_bounds__(256)
void k_gather(const float* __restrict__ in, float* __restrict__ out_q) {
    __shared__ float q_s[128 * 68];
    __shared__ int   idx_s[128];
    __shared__ float part[8];
    const int tid = threadIdx.x;
    const int token0 = blockIdx.x * 128;
    const int b   = token0 >> 12;
    const int hw0 = token0 & 4095;

    if (tid < 128) idx_s[tid] = g_idx[token0 + tid];
    __syncthreads();

#pragma unroll
    for (int r = 0; r < 8; r++) {
        int m  = r * 256 + tid;
        int t  = m >> 4;
        int sg = (m & 15) * 4;
        float4 v = *(const float4*)(g_neww + idx_s[t] * 64 + sg);
        *(float4*)(q_s + t * 68 + sg) = v;
    }
    __syncthreads();

    const size_t base = (size_t)b * CHW + hw0;
    float lsum = 0.f;
#pragma unroll 4
    for (int it = 0; it < 32; it++) {
        int d = it * 2 + (tid >> 7);
        int t = tid & 127;
        size_t gidx = base + (size_t)d * HW + t;
        float x  = in[gidx];
        float q  = q_s[t * 68 + d];
        float dt = q - x;
        out_q[gidx] = x + dt;
        lsum = fmaf(dt, dt, lsum);
    }
#pragma unroll
    for (int off = 16; off > 0; off >>= 1)
        lsum += __shfl_xor_sync(0xffffffffu, lsum, off);
    if ((tid & 31) == 0) part[tid >> 5] = lsum;
    __syncthreads();
    if (tid == 0) {
        float s = 0.f;
#pragma unroll
        for (int i = 0; i < 8; i++) s += part[i];
        atomicAdd(&g_loss, s);
    }
}

// ---------------- kernel 6: finalize loss ----------------
__global__ void k_final(float* out) {
    out[0] = 0.25f * (g_loss * (1.0f / 16777216.0f));
}

// ---------------- launch ----------------
extern "C" void kernel_launch(void* const* d_in, const int* in_sizes, int n_in,
                              void* d_out, int out_size) {
    const float* in  = (const float*)d_in[0];   // (64,64,64,64) NCHW
    const float* w   = (const float*)d_in[1];   // (1024,64)
    const float* ecs = (const float*)d_in[2];   // (1024,)
    const float* ew  = (const float*)d_in[3];   // (1024,64)
    float* out      = (float*)d_out;            // [loss | quantized NCHW | idx]
    float* out_q    = out + 1;
    float* out_idx  = out + 1 + Q_ELEMS;

    const int ARG_SMEM = 65536 + 32768 + 512 + 1024;   // 99840 B

    k_zero<<<(K_CODES * D_DIM + 255) / 256, 256>>>();
    k_prep<<<4, 256>>>(w);
    k_pack<<<64, 256>>>(w);
    cudaFuncSetAttribute(k_argmin, cudaFuncAttributeMaxDynamicSharedMemorySize, ARG_SMEM);
    k_argmin<<<N_TOK / 256, 256, ARG_SMEM>>>(in, out_idx);
    k_fix3<<<148, 256>>>(in, w, out_idx);
    k_update<<<1, 1024>>>(ecs, ew);
    k_gather<<<N_TOK / 128, 256>>>(in, out_q);
    k_final<<<1, 1>>>(out);
}

// round 8
// speedup vs baseline: 2.3165x; 1.4259x over previous
#include <cuda_runtime.h>
#include <cuda_fp16.h>
#include <math_constants.h>

#define N_TOK   262144
#define K_CODES 1024
#define D_DIM   64
#define HW      4096
#define CHW     262144
#define Q_ELEMS 16777216
#define GAP_T   5e-4f          // fp16-split eps ~1e-5 -> 50x margin
#define FIXCAP  65536

// ---------------- scratch (device globals; no allocation allowed) ----------------
__device__ uint4  g_Wpack[8 * 16 * 4 * 32];  // fragment-packed codebook {bh0,bh1,bl0,bl1}
__device__ float  g_wnh[K_CODES];            // 0.5*||w_k||^2 (fp32)
__device__ double g_wnh64[K_CODES];          // 0.5*||w_k||^2 (fp64, for exact repair)
__device__ float  g_counts[K_CODES];
__device__ float  g_dw[K_CODES * D_DIM];
__device__ float  g_neww[K_CODES * D_DIM];
__device__ float  g_loss;
__device__ float  g_n;
__device__ int    g_idx[N_TOK];
__device__ int    g_nfix;
__device__ int    g_fixlist[FIXCAP];

// ---------------- helpers ----------------
__device__ __forceinline__ unsigned h2_bits(__half2 h) {
    return *reinterpret_cast<unsigned*>(&h);
}
__device__ __forceinline__ void split_pair(float xa, float xb,
                                           unsigned& hi, unsigned& lo) {
    __half2 h = __floats2half2_rn(xa, xb);
    float2 hf = __half22float2(h);
    __half2 l = __floats2half2_rn(xa - hf.x, xb - hf.y);
    hi = h2_bits(h);
    lo = h2_bits(l);
}
__device__ __forceinline__ void mma16816(float* c, const unsigned* a,
                                         unsigned b0, unsigned b1) {
    asm("mma.sync.aligned.m16n8k16.row.col.f32.f16.f16.f32 "
        "{%0,%1,%2,%3}, {%4,%5,%6,%7}, {%8,%9}, {%0,%1,%2,%3};"
        : "+f"(c[0]), "+f"(c[1]), "+f"(c[2]), "+f"(c[3])
        : "r"(a[0]), "r"(a[1]), "r"(a[2]), "r"(a[3]), "r"(b0), "r"(b1));
}

// ---------------- kernel 1: zero + coalesced norms (warp per code) ----------------
// 128 blocks x 256 threads = 1024 warps; warp w owns code w.
__global__ __launch_bounds__(256)
void k_prep(const float* __restrict__ w) {
    const int gt   = blockIdx.x * 256 + threadIdx.x;   // 0..32767
    const int kcode = gt >> 5;
    const int lane  = gt & 31;

    // zeroing (distinct addresses, same launch, pre-argmin in stream order)
    if (gt < K_CODES) g_counts[gt] = 0.f;
    g_dw[gt * 2]     = 0.f;
    g_dw[gt * 2 + 1] = 0.f;
    if (gt == 0) { g_loss = 0.f; g_nfix = 0; }

    float  v1 = w[kcode * 64 + lane];
    float  v2 = w[kcode * 64 + 32 + lane];
    double sd = (double)v1 * v1 + (double)v2 * v2;
#pragma unroll
    for (int off = 16; off > 0; off >>= 1)
        sd += __shfl_xor_sync(0xffffffffu, sd, off);
    if (lane == 0) {
        g_wnh64[kcode] = 0.5 * sd;
        g_wnh[kcode]   = (float)(0.5 * sd);
    }
}

// ---------------- kernel 2: pack codebook into mma B-fragment order --------------
__global__ void k_pack(const float* __restrict__ w) {
    int item = blockIdx.x * 256 + threadIdx.x;    // 0..16383
    int lane = item & 31;
    int kst  = (item >> 5) & 3;
    int nt   = (item >> 7) & 15;
    int kt   = item >> 11;
    int n = kt * 128 + nt * 8 + (lane >> 2);
    int k = kst * 16 + 2 * (lane & 3);
    const float* wr = w + n * 64;
    unsigned h0, l0, h1, l1;
    split_pair(wr[k],     wr[k + 1], h0, l0);
    split_pair(wr[k + 8], wr[k + 9], h1, l1);
    g_Wpack[item] = make_uint4(h0, h1, l0, l1);
}

// ---------------- kernel 3: tensor-core distances + top-2 + scatters + flags ------
__global__ __launch_bounds__(256)
void k_argmin(const float* __restrict__ in, float* __restrict__ out_idx_f) {
    extern __shared__ char smem[];
    float* A_s   = (float*)smem;                       // [64][256] d-major (64 KB)
    uint4* Wt4   = (uint4*)(smem + 65536);             // 2048 uint4 (32 KB)
    float* wn_s  = (float*)(smem + 65536 + 32768);     // [128]
    int*   idx_s = (int*)(smem + 65536 + 32768 + 512); // [256]

    const int tid  = threadIdx.x;
    const int warp = tid >> 5;
    const int lane = tid & 31;
    const int g    = lane >> 2;
    const int t    = lane & 3;
    const int token0 = blockIdx.x * 256;
    const int b   = token0 >> 12;
    const int hw0 = token0 & 4095;
    const float* Abase = in + (size_t)b * CHW + hw0;

#pragma unroll
    for (int r = 0; r < 16; r++) {
        int m = r * 256 + tid;
        int d = m >> 6;
        int c = (m & 63) * 4;
        *(float4*)(A_s + d * 256 + c) = *(const float4*)(Abase + (size_t)d * HW + c);
    }
    __syncthreads();

    unsigned Ah[2][4][4], Al[2][4][4];
#pragma unroll
    for (int mt = 0; mt < 2; mt++) {
        int r0 = warp * 32 + mt * 16 + g;
        int r1 = r0 + 8;
#pragma unroll
        for (int kst = 0; kst < 4; kst++) {
            int kb = kst * 16;
#pragma unroll
            for (int f = 0; f < 4; f++) {
                int row = (f & 1) ? r1 : r0;
                int kk  = kb + 2 * t + ((f >> 1) ? 8 : 0);
                split_pair(A_s[kk * 256 + row], A_s[(kk + 1) * 256 + row],
                           Ah[mt][kst][f], Al[mt][kst][f]);
            }
        }
    }

    float rs1[4], rs2[4];
    int   rk1[4];
#pragma unroll
    for (int i = 0; i < 4; i++) { rs1[i] = CUDART_INF_F; rs2[i] = CUDART_INF_F; rk1[i] = 0; }

    for (int kt = 0; kt < 8; kt++) {
        __syncthreads();
#pragma unroll
        for (int r = 0; r < 8; r++)
            Wt4[r * 256 + tid] = g_Wpack[kt * 2048 + r * 256 + tid];
        if (tid < 32) ((float4*)wn_s)[tid] = ((const float4*)(g_wnh + kt * 128))[tid];
        __syncthreads();

        for (int nt = 0; nt < 16; nt++) {
            float c0[4] = {0.f, 0.f, 0.f, 0.f};
            float c1[4] = {0.f, 0.f, 0.f, 0.f};
#pragma unroll
            for (int kst = 0; kst < 4; kst++) {
                uint4 bp = Wt4[(nt * 4 + kst) * 32 + lane];
                mma16816(c0, Ah[0][kst], bp.x, bp.y);
                mma16816(c0, Al[0][kst], bp.x, bp.y);
                mma16816(c0, Ah[0][kst], bp.z, bp.w);
                mma16816(c1, Ah[1][kst], bp.x, bp.y);
                mma16816(c1, Al[1][kst], bp.x, bp.y);
                mma16816(c1, Ah[1][kst], bp.z, bp.w);
            }
            float wa = wn_s[nt * 8 + 2 * t];
            float wb = wn_s[nt * 8 + 2 * t + 1];
            int   ka = kt * 128 + nt * 8 + 2 * t;
#pragma unroll
            for (int rr = 0; rr < 4; rr++) {
                const float* cc = (rr < 2) ? c0 : c1;
                float sa = wa - cc[(rr & 1) ? 2 : 0];
                float sb = wb - cc[(rr & 1) ? 3 : 1];
                bool pa = sa < rs1[rr];
                rs2[rr] = fminf(rs2[rr], fmaxf(rs1[rr], sa));
                rs1[rr] = fminf(rs1[rr], sa);
                rk1[rr] = pa ? ka : rk1[rr];
                bool pb = sb < rs1[rr];
                rs2[rr] = fminf(rs2[rr], fmaxf(rs1[rr], sb));
                rs1[rr] = fminf(rs1[rr], sb);
                rk1[rr] = pb ? (ka + 1) : rk1[rr];
            }
        }
    }

#pragma unroll
    for (int rr = 0; rr < 4; rr++) {
#pragma unroll
        for (int off = 1; off <= 2; off <<= 1) {
            float o1 = __shfl_xor_sync(0xffffffffu, rs1[rr], off, 4);
            int   ok = __shfl_xor_sync(0xffffffffu, rk1[rr], off, 4);
            float o2 = __shfl_xor_sync(0xffffffffu, rs2[rr], off, 4);
            float n1 = fminf(rs1[rr], o1);
            float n2 = fminf(fmaxf(rs1[rr], o1), fminf(rs2[rr], o2));
            rk1[rr] = (o1 < rs1[rr] || (o1 == rs1[rr] && ok < rk1[rr])) ? ok : rk1[rr];
            rs1[rr] = n1; rs2[rr] = n2;
        }
    }
    __syncthreads();
    if (t == 0) {
#pragma unroll
        for (int rr = 0; rr < 4; rr++) {
            int L = warp * 32 + (rr >> 1) * 16 + (rr & 1) * 8 + g;
            idx_s[L] = rk1[rr];
            if (rs2[rr] - rs1[rr] < GAP_T) {
                int pos = atomicAdd(&g_nfix, 1);
                if (pos < FIXCAP) g_fixlist[pos] = token0 + L;
            }
        }
    }
    __syncthreads();

    {
        int k = idx_s[tid];
        atomicAdd(&g_counts[k], 1.0f);
        g_idx[token0 + tid]     = k;
        out_idx_f[token0 + tid] = (float)k;
    }

#pragma unroll
    for (int it = 0; it < 16; it++) {
        int m   = it * 256 + tid;
        int tkn = m & 255;
        int q   = m >> 8;
        float a0 = A_s[(q * 4 + 0) * 256 + tkn];
        float a1 = A_s[(q * 4 + 1) * 256 + tkn];
        float a2 = A_s[(q * 4 + 2) * 256 + tkn];
        float a3 = A_s[(q * 4 + 3) * 256 + tkn];
        float* p = g_dw + idx_s[tkn] * 64 + q * 4;
        asm volatile("red.global.add.v4.f32 [%0], {%1, %2, %3, %4};"
                     :: "l"(p), "f"(a0), "f"(a1), "f"(a2), "f"(a3) : "memory");
    }
}

// ---------------- kernel 3b: fp64 score-form full-scan repair ----------------
__global__ __launch_bounds__(256)
void k_fix3(const float* __restrict__ in, const float* __restrict__ w,
            float* __restrict__ out_idx_f) {
    __shared__ float xs[8][64];
    int n = g_nfix; if (n > FIXCAP) n = FIXCAP;
    const int warp = threadIdx.x >> 5;
    const int lane = threadIdx.x & 31;
    for (int i = blockIdx.x * 8 + warp; i < n; i += gridDim.x * 8) {
        int t = g_fixlist[i];
        const float* x = in + (size_t)(t >> 12) * CHW + (t & 4095);
        xs[warp][lane]      = x[(size_t)lane * HW];
        xs[warp][lane + 32] = x[(size_t)(lane + 32) * HW];
        __syncwarp();

        double bd = CUDART_INF;
        int    bk = 0x7fffffff;
        for (int jj = 0; jj < 8; jj++) {
            int    c[4];
            double acc[4] = {0.0, 0.0, 0.0, 0.0};
#pragma unroll
            for (int u = 0; u < 4; u++) c[u] = (jj + u * 8) * 32 + lane;
#pragma unroll 4
            for (int q = 0; q < 16; q++) {
                float4 wv[4];
#pragma unroll
                for (int u = 0; u < 4; u++)
                    wv[u] = ((const float4*)(w + c[u] * 64))[q];
#pragma unroll
                for (int r = 0; r < 4; r++) {
                    double xv = (double)xs[warp][q * 4 + r];
#pragma unroll
                    for (int u = 0; u < 4; u++)
                        acc[u] = fma(xv, (double)((&wv[u].x)[r]), acc[u]);
                }
            }
#pragma unroll
            for (int u = 0; u < 4; u++) {
                double s = g_wnh64[c[u]] - acc[u];       // 0.5||w||^2 - x.w
                if (s < bd || (s == bd && c[u] < bk)) { bd = s; bk = c[u]; }
            }
        }
#pragma unroll
        for (int off = 16; off > 0; off >>= 1) {
            double od = __shfl_xor_sync(0xffffffffu, bd, off);
            int    ok = __shfl_xor_sync(0xffffffffu, bk, off);
            if (od < bd || (od == bd && ok < bk)) { bd = od; bk = ok; }
        }
        if (lane == 0) {
            int old = g_idx[t];
            if (bk != old) {
                g_idx[t]     = bk;
                out_idx_f[t] = (float)bk;
                atomicAdd(&g_counts[old], -1.0f);
                atomicAdd(&g_counts[bk],   1.0f);
                for (int d = 0; d < 64; d++) {
                    float xv = xs[warp][d];
                    atomicAdd(&g_dw[old * 64 + d], -xv);
                    atomicAdd(&g_dw[bk  * 64 + d],  xv);
                }
            }
        }
        __syncwarp();
    }
}

// ---------------- kernel 4a: reduce n = sum(cs) ----------------
__global__ void k_sum(const float* __restrict__ ecs) {
    __shared__ float red[1024];
    int k = threadIdx.x;
    red[k] = ecs[k] * 0.99f + 0.01f * g_counts[k];
    __syncthreads();
    for (int s = 512; s > 0; s >>= 1) {
        if (k < s) red[k] += red[k + s];
        __syncthreads();
    }
    if (k == 0) g_n = red[0];
}

// ---------------- kernel 4b: EMA update, fully coalesced ----------------
__global__ __launch_bounds__(256)
void k_updw(const float* __restrict__ ecs, const float* __restrict__ ew) {
    int i = blockIdx.x * 256 + threadIdx.x;     // 0..65535
    int k = i >> 6;
    float n  = g_n;
    float cs = ecs[k] * 0.99f + 0.01f * g_counts[k];
    float csn = (cs + 1e-5f) / (n + 1024.0f * 1e-5f) * n;
    float e = ew[i] * 0.99f + 0.01f * g_dw[i];
    g_neww[i] = e / csn;
}

// ---------------- kernel 5: gather + straight-through + loss partials -------------
__global__ __launch_bounds__(256)
void k_gather(const float* __restrict__ in, float* __restrict__ out_q) {
    __shared__ float q_s[128 * 68];
    __shared__ int   idx_s[128];
    __shared__ float part[8];
    const int tid = threadIdx.x;
    const int token0 = blockIdx.x * 128;
    const int b   = token0 >> 12;
    const int hw0 = token0 & 4095;

    if (tid < 128) idx_s[tid] = g_idx[token0 + tid];
    __syncthreads();

#pragma unroll
    for (int r = 0; r < 8; r++) {
        int m  = r * 256 + tid;
        int t  = m >> 4;
        int sg = (m & 15) * 4;
        float4 v = *(const float4*)(g_neww + idx_s[t] * 64 + sg);
        *(float4*)(q_s + t * 68 + sg) = v;
    }
    __syncthreads();

    const size_t base = (size_t)b * CHW + hw0;
    float lsum = 0.f;
#pragma unroll 4
    for (int it = 0; it < 32; it++) {
        int d = it * 2 + (tid >> 7);
        int t = tid & 127;
        size_t gidx = base + (size_t)d * HW + t;
        float x  = in[gidx];
        float q  = q_s[t * 68 + d];
        float dt = q - x;
        out_q[gidx] = x + dt;
        lsum = fmaf(dt, dt, lsum);
    }
#pragma unroll
    for (int off = 16; off > 0; off >>= 1)
        lsum += __shfl_xor_sync(0xffffffffu, lsum, off);
    if ((tid & 31) == 0) part[tid >> 5] = lsum;
    __syncthreads();
    if (tid == 0) {
        float s = 0.f;
#pragma unroll
        for (int i = 0; i < 8; i++) s += part[i];
        atomicAdd(&g_loss, s);
    }
}

// ---------------- kernel 6: finalize loss ----------------
__global__ void k_final(float* out) {
    out[0] = 0.25f * (g_loss * (1.0f / 16777216.0f));
}

// ---------------- launch ----------------
extern "C" void kernel_launch(void* const* d_in, const int* in_sizes, int n_in,
                              void* d_out, int out_size) {
    const float* in  = (const float*)d_in[0];   // (64,64,64,64) NCHW
    const float* w   = (const float*)d_in[1];   // (1024,64)
    const float* ecs = (const float*)d_in[2];   // (1024,)
    const float* ew  = (const float*)d_in[3];   // (1024,64)
    float* out      = (float*)d_out;            // [loss | quantized NCHW | idx]
    float* out_q    = out + 1;
    float* out_idx  = out + 1 + Q_ELEMS;

    const int ARG_SMEM = 65536 + 32768 + 512 + 1024;   // 99840 B

    k_prep<<<128, 256>>>(w);
    k_pack<<<64, 256>>>(w);
    cudaFuncSetAttribute(k_argmin, cudaFuncAttributeMaxDynamicSharedMemorySize, ARG_SMEM);
    k_argmin<<<N_TOK / 256, 256, ARG_SMEM>>>(in, out_idx);
    k_fix3<<<256, 256>>>(in, w, out_idx);
    k_sum<<<1, 1024>>>(ecs);
    k_updw<<<256, 256>>>(ecs, ew);
    k_gather<<<N_TOK / 128, 256>>>(in, out_q);
    k_final<<<1, 1>>>(out);
}

// round 9
// speedup vs baseline: 4.2150x; 1.8196x over previous
#include <cuda_runtime.h>
#include <cuda_fp16.h>
#include <math_constants.h>

#define N_TOK   262144
#define K_CODES 1024
#define D_DIM   64
#define HW      4096
#define CHW     262144
#define Q_ELEMS 16777216
#define GAP_T   5e-4f          // >= 2x worst-case fp16-split+fp32-accum noise bound
#define FIXCAP  65536

// ---------------- scratch (device globals; no allocation allowed) ----------------
__device__ uint4  g_Wpack[8 * 16 * 4 * 32];  // fragment-packed codebook {bh0,bh1,bl0,bl1}
__device__ float  g_wnh[K_CODES];            // 0.5*||w_k||^2 (fp32)
__device__ double g_wnh64[K_CODES];          // 0.5*||w_k||^2 (fp64, for exact repair)
__device__ float  g_counts[K_CODES];
__device__ float  g_dw[K_CODES * D_DIM];
__device__ float  g_neww[K_CODES * D_DIM];
__device__ float  g_loss;
__device__ float  g_n;
__device__ int    g_idx[N_TOK];
__device__ int    g_nfix;
__device__ int4   g_fixlist[FIXCAP];         // {token, k1, k2, tier2?}

// ---------------- helpers ----------------
__device__ __forceinline__ unsigned h2_bits(__half2 h) {
    return *reinterpret_cast<unsigned*>(&h);
}
__device__ __forceinline__ void split_pair(float xa, float xb,
                                           unsigned& hi, unsigned& lo) {
    __half2 h = __floats2half2_rn(xa, xb);
    float2 hf = __half22float2(h);
    __half2 l = __floats2half2_rn(xa - hf.x, xb - hf.y);
    hi = h2_bits(h);
    lo = h2_bits(l);
}
__device__ __forceinline__ void mma16816(float* c, const unsigned* a,
                                         unsigned b0, unsigned b1) {
    asm("mma.sync.aligned.m16n8k16.row.col.f32.f16.f16.f32 "
        "{%0,%1,%2,%3}, {%4,%5,%6,%7}, {%8,%9}, {%0,%1,%2,%3};"
        : "+f"(c[0]), "+f"(c[1]), "+f"(c[2]), "+f"(c[3])
        : "r"(a[0]), "r"(a[1]), "r"(a[2]), "r"(a[3]), "r"(b0), "r"(b1));
}
__device__ __forceinline__ bool lt2(float s, int k, float s2, int k2) {
    return (s < s2) || (s == s2 && k < k2);
}
// top-3 insert: scores rs1<=rs2<=rs3, packed indices rk12 = (k2<<16)|k1
__device__ __forceinline__ void ins3(float s, int k,
                                     float& rs1, float& rs2, float& rs3,
                                     unsigned& rk12) {
    bool pa = s < rs1;
    bool pb = s < rs2;
    float nrs3 = pb ? rs2 : fminf(rs3, s);
    float nrs2 = pa ? rs1 : fminf(rs2, s);
    unsigned ca = (rk12 << 16) | (unsigned)k;              // old k1 -> k2, k -> k1
    unsigned cb = ((unsigned)k << 16) | (rk12 & 0xffffu);  // k -> k2
    rk12 = pa ? ca : (pb ? cb : rk12);
    rs1 = fminf(rs1, s);
    rs2 = nrs2;
    rs3 = nrs3;
}

// ---------------- kernel 1: zero + coalesced norms (warp per code) ----------------
__global__ __launch_bounds__(256)
void k_prep(const float* __restrict__ w) {
    const int gt    = blockIdx.x * 256 + threadIdx.x;   // 0..32767
    const int kcode = gt >> 5;
    const int lane  = gt & 31;

    if (gt < K_CODES) g_counts[gt] = 0.f;
    g_dw[gt * 2]     = 0.f;
    g_dw[gt * 2 + 1] = 0.f;
    if (gt == 0) { g_loss = 0.f; g_nfix = 0; }

    float  v1 = w[kcode * 64 + lane];
    float  v2 = w[kcode * 64 + 32 + lane];
    double sd = (double)v1 * v1 + (double)v2 * v2;
#pragma unroll
    for (int off = 16; off > 0; off >>= 1)
        sd += __shfl_xor_sync(0xffffffffu, sd, off);
    if (lane == 0) {
        g_wnh64[kcode] = 0.5 * sd;
        g_wnh[kcode]   = (float)(0.5 * sd);
    }
}

// ---------------- kernel 2: pack codebook into mma B-fragment order --------------
__global__ void k_pack(const float* __restrict__ w) {
    int item = blockIdx.x * 256 + threadIdx.x;    // 0..16383
    int lane = item & 31;
    int kst  = (item >> 5) & 3;
    int nt   = (item >> 7) & 15;
    int kt   = item >> 11;
    int n = kt * 128 + nt * 8 + (lane >> 2);
    int k = kst * 16 + 2 * (lane & 3);
    const float* wr = w + n * 64;
    unsigned h0, l0, h1, l1;
    split_pair(wr[k],     wr[k + 1], h0, l0);
    split_pair(wr[k + 8], wr[k + 9], h1, l1);
    g_Wpack[item] = make_uint4(h0, h1, l0, l1);
}

// ---------------- kernel 3: tensor-core distances + top-3 + scatters + flags ------
__global__ __launch_bounds__(256, 2)
void k_argmin(const float* __restrict__ in, float* __restrict__ out_idx_f) {
    extern __shared__ char smem[];
    float* A_s   = (float*)smem;                       // [64][256] d-major (64 KB)
    uint4* Wt4   = (uint4*)(smem + 65536);             // 2048 uint4 (32 KB)
    float* wn_s  = (float*)(smem + 65536 + 32768);     // [128]
    int*   idx_s = (int*)(smem + 65536 + 32768 + 512); // [256]

    const int tid  = threadIdx.x;
    const int warp = tid >> 5;
    const int lane = tid & 31;
    const int g    = lane >> 2;
    const int t    = lane & 3;
    const int token0 = blockIdx.x * 256;
    const int b   = token0 >> 12;
    const int hw0 = token0 & 4095;
    const float* Abase = in + (size_t)b * CHW + hw0;

#pragma unroll
    for (int r = 0; r < 16; r++) {
        int m = r * 256 + tid;
        int d = m >> 6;
        int c = (m & 63) * 4;
        *(float4*)(A_s + d * 256 + c) = *(const float4*)(Abase + (size_t)d * HW + c);
    }
    __syncthreads();

    unsigned Ah[2][4][4], Al[2][4][4];
#pragma unroll
    for (int mt = 0; mt < 2; mt++) {
        int r0 = warp * 32 + mt * 16 + g;
        int r1 = r0 + 8;
#pragma unroll
        for (int kst = 0; kst < 4; kst++) {
            int kb = kst * 16;
#pragma unroll
            for (int f = 0; f < 4; f++) {
                int row = (f & 1) ? r1 : r0;
                int kk  = kb + 2 * t + ((f >> 1) ? 8 : 0);
                split_pair(A_s[kk * 256 + row], A_s[(kk + 1) * 256 + row],
                           Ah[mt][kst][f], Al[mt][kst][f]);
            }
        }
    }

    float    rs1[4], rs2[4], rs3[4];
    unsigned rk12[4];
#pragma unroll
    for (int i = 0; i < 4; i++) {
        rs1[i] = CUDART_INF_F; rs2[i] = CUDART_INF_F; rs3[i] = CUDART_INF_F; rk12[i] = 0;
    }

    for (int kt = 0; kt < 8; kt++) {
        __syncthreads();
#pragma unroll
        for (int r = 0; r < 8; r++)
            Wt4[r * 256 + tid] = g_Wpack[kt * 2048 + r * 256 + tid];
        if (tid < 32) ((float4*)wn_s)[tid] = ((const float4*)(g_wnh + kt * 128))[tid];
        __syncthreads();

        for (int nt = 0; nt < 16; nt++) {
            float c0[4] = {0.f, 0.f, 0.f, 0.f};
            float c1[4] = {0.f, 0.f, 0.f, 0.f};
#pragma unroll
            for (int kst = 0; kst < 4; kst++) {
                uint4 bp = Wt4[(nt * 4 + kst) * 32 + lane];
                mma16816(c0, Ah[0][kst], bp.x, bp.y);
                mma16816(c0, Al[0][kst], bp.x, bp.y);
                mma16816(c0, Ah[0][kst], bp.z, bp.w);
                mma16816(c1, Ah[1][kst], bp.x, bp.y);
                mma16816(c1, Al[1][kst], bp.x, bp.y);
                mma16816(c1, Ah[1][kst], bp.z, bp.w);
            }
            float wa = wn_s[nt * 8 + 2 * t];
            float wb = wn_s[nt * 8 + 2 * t + 1];
            int   ka = kt * 128 + nt * 8 + 2 * t;
#pragma unroll
            for (int rr = 0; rr < 4; rr++) {
                const float* cc = (rr < 2) ? c0 : c1;
                float sa = wa - cc[(rr & 1) ? 2 : 0];
                float sb = wb - cc[(rr & 1) ? 3 : 1];
                ins3(sa, ka,     rs1[rr], rs2[rr], rs3[rr], rk12[rr]);
                ins3(sb, ka + 1, rs1[rr], rs2[rr], rs3[rr], rk12[rr]);
            }
        }
    }

    // merge top-3 across the 4-lane column group
#pragma unroll
    for (int rr = 0; rr < 4; rr++) {
#pragma unroll
        for (int off = 1; off <= 2; off <<= 1) {
            float    o1 = __shfl_xor_sync(0xffffffffu, rs1[rr], off, 4);
            float    o2 = __shfl_xor_sync(0xffffffffu, rs2[rr], off, 4);
            float    o3 = __shfl_xor_sync(0xffffffffu, rs3[rr], off, 4);
            unsigned oj = __shfl_xor_sync(0xffffffffu, rk12[rr], off, 4);
            int j1 = oj & 0xffff, j2 = oj >> 16;
            float a1 = rs1[rr], a2 = rs2[rr], a3 = rs3[rr];
            int ak1 = rk12[rr] & 0xffff, ak2 = rk12[rr] >> 16;
            if (lt2(o1, j1, a1, ak1)) {
                rs1[rr] = o1;
                if (lt2(a1, ak1, o2, j2)) {
                    rk12[rr] = ((unsigned)ak1 << 16) | (unsigned)j1;
                    rs2[rr] = a1; rs3[rr] = fminf(a2, o2);
                } else {
                    rk12[rr] = ((unsigned)j2 << 16) | (unsigned)j1;
                    rs2[rr] = o2; rs3[rr] = fminf(a1, o3);
                }
            } else {
                if (lt2(o1, j1, a2, ak2)) {
                    rk12[rr] = ((unsigned)j1 << 16) | (unsigned)ak1;
                    rs2[rr] = o1; rs3[rr] = fminf(a2, o2);
                } else {
                    rs3[rr] = fminf(o1, a3);
                }
            }
        }
    }
    __syncthreads();
    if (t == 0) {
#pragma unroll
        for (int rr = 0; rr < 4; rr++) {
            int L = warp * 32 + (rr >> 1) * 16 + (rr & 1) * 8 + g;
            int k1 = rk12[rr] & 0xffff;
            idx_s[L] = k1;
            if (rs2[rr] - rs1[rr] < GAP_T) {
                int tier2 = (rs3[rr] - rs1[rr] < GAP_T) ? 1 : 0;
                int pos = atomicAdd(&g_nfix, 1);
                if (pos < FIXCAP)
                    g_fixlist[pos] = make_int4(token0 + L, k1, (int)(rk12[rr] >> 16), tier2);
            }
        }
    }
    __syncthreads();

    {
        int k = idx_s[tid];
        atomicAdd(&g_counts[k], 1.0f);
        g_idx[token0 + tid]     = k;
        out_idx_f[token0 + tid] = (float)k;
    }

#pragma unroll
    for (int it = 0; it < 16; it++) {
        int m   = it * 256 + tid;
        int tkn = m & 255;
        int q   = m >> 8;
        float a0 = A_s[(q * 4 + 0) * 256 + tkn];
        float a1 = A_s[(q * 4 + 1) * 256 + tkn];
        float a2 = A_s[(q * 4 + 2) * 256 + tkn];
        float a3 = A_s[(q * 4 + 3) * 256 + tkn];
        float* p = g_dw + idx_s[tkn] * 64 + q * 4;
        asm volatile("red.global.add.v4.f32 [%0], {%1, %2, %3, %4};"
                     :: "l"(p), "f"(a0), "f"(a1), "f"(a2), "f"(a3) : "memory");
    }
}

// ---------------- kernel 3b: two-tier fp64 repair ----------------
// tier1 (s3 gap safe): pair-compare k1 vs k2. tier2: full 1024-code scan.
__global__ __launch_bounds__(256)
void k_fix4(const float* __restrict__ in, const float* __restrict__ w,
            float* __restrict__ out_idx_f) {
    __shared__ float xs[8][64];
    int n = g_nfix; if (n > FIXCAP) n = FIXCAP;
    const int warp = threadIdx.x >> 5;
    const int lane = threadIdx.x & 31;
    for (int i = blockIdx.x * 8 + warp; i < n; i += gridDim.x * 8) {
        int4 e = g_fixlist[i];
        const int t = e.x;
        const float* x = in + (size_t)(t >> 12) * CHW + (t & 4095);
        float xv1f = x[(size_t)lane * HW];
        float xv2f = x[(size_t)(lane + 32) * HW];

        int bk;
        if (!e.w) {
            // ---- tier 1: exact pair compare ----
            double xv1 = (double)xv1f, xv2 = (double)xv2f;
            double d1 = xv1 * (double)w[e.y * 64 + lane]
                      + xv2 * (double)w[e.y * 64 + 32 + lane];
            double d2 = xv1 * (double)w[e.z * 64 + lane]
                      + xv2 * (double)w[e.z * 64 + 32 + lane];
#pragma unroll
            for (int off = 16; off > 0; off >>= 1) {
                d1 += __shfl_xor_sync(0xffffffffu, d1, off);
                d2 += __shfl_xor_sync(0xffffffffu, d2, off);
            }
            double s1 = g_wnh64[e.y] - d1;
            double s2 = g_wnh64[e.z] - d2;
            bk = (s2 < s1 || (s2 == s1 && e.z < e.y)) ? e.z : e.y;
        } else {
            // ---- tier 2: exact full scan ----
            xs[warp][lane]      = xv1f;
            xs[warp][lane + 32] = xv2f;
            __syncwarp();
            double bd = CUDART_INF;
            bk = 0x7fffffff;
            for (int jj = 0; jj < 8; jj++) {
                int    c[4];
                double acc[4] = {0.0, 0.0, 0.0, 0.0};
#pragma unroll
                for (int u = 0; u < 4; u++) c[u] = (jj + u * 8) * 32 + lane;
#pragma unroll 4
                for (int q = 0; q < 16; q++) {
                    float4 wv[4];
#pragma unroll
                    for (int u = 0; u < 4; u++)
                        wv[u] = ((const float4*)(w + c[u] * 64))[q];
#pragma unroll
                    for (int r = 0; r < 4; r++) {
                        double xv = (double)xs[warp][q * 4 + r];
#pragma unroll
                        for (int u = 0; u < 4; u++)
                            acc[u] = fma(xv, (double)((&wv[u].x)[r]), acc[u]);
                    }
                }
#pragma unroll
                for (int u = 0; u < 4; u++) {
                    double s = g_wnh64[c[u]] - acc[u];
                    if (s < bd || (s == bd && c[u] < bk)) { bd = s; bk = c[u]; }
                }
            }
#pragma unroll
            for (int off = 16; off > 0; off >>= 1) {
                double od = __shfl_xor_sync(0xffffffffu, bd, off);
                int    ok = __shfl_xor_sync(0xffffffffu, bk, off);
                if (od < bd || (od == bd && ok < bk)) { bd = od; bk = ok; }
            }
            __syncwarp();
        }

        int old = e.y;                       // current assignment is k1
        if (bk != old) {
            if (lane == 0) {
                g_idx[t]     = bk;
                out_idx_f[t] = (float)bk;
                atomicAdd(&g_counts[old], -1.0f);
                atomicAdd(&g_counts[bk],   1.0f);
            }
            atomicAdd(&g_dw[old * 64 + lane],      -xv1f);
            atomicAdd(&g_dw[old * 64 + 32 + lane], -xv2f);
            atomicAdd(&g_dw[bk  * 64 + lane],       xv1f);
            atomicAdd(&g_dw[bk  * 64 + 32 + lane],  xv2f);
        }
    }
}

// ---------------- kernel 4a: reduce n = sum(cs) ----------------
__global__ void k_sum(const float* __restrict__ ecs) {
    __shared__ float red[1024];
    int k = threadIdx.x;
    red[k] = ecs[k] * 0.99f + 0.01f * g_counts[k];
    __syncthreads();
    for (int s = 512; s > 0; s >>= 1) {
        if (k < s) red[k] += red[k + s];
        __syncthreads();
    }
    if (k == 0) g_n = red[0];
}

// ---------------- kernel 4b: EMA update, fully coalesced ----------------
__global__ __launch_bounds__(256)
void k_updw(const float* __restrict__ ecs, const float* __restrict__ ew) {
    int i = blockIdx.x * 256 + threadIdx.x;     // 0..65535
    int k = i >> 6;
    float n  = g_n;
    float cs = ecs[k] * 0.99f + 0.01f * g_counts[k];
    float csn = (cs + 1e-5f) / (n + 1024.0f * 1e-5f) * n;
    float e = ew[i] * 0.99f + 0.01f * g_dw[i];
    g_neww[i] = e / csn;
}

// ---------------- kernel 5: gather + straight-through + loss partials -------------
__global__ __launch_bounds__(256)
void k_gather(const float* __restrict__ in, float* __restrict__ out_q) {
    __shared__ float q_s[128 * 68];
    __shared__ int   idx_s[128];
    __shared__ float part[8];
    const int tid = threadIdx.x;
    const int token0 = blockIdx.x * 128;
    const int b   = token0 >> 12;
    const int hw0 = token0 & 4095;

    if (tid < 128) idx_s[tid] = g_idx[token0 + tid];
    __syncthreads();

#pragma unroll
    for (int r = 0; r < 8; r++) {
        int m  = r * 256 + tid;
        int t  = m >> 4;
        int sg = (m & 15) * 4;
        float4 v = *(const float4*)(g_neww + idx_s[t] * 64 + sg);
        *(float4*)(q_s + t * 68 + sg) = v;
    }
    __syncthreads();

    const size_t base = (size_t)b * CHW + hw0;
    float lsum = 0.f;
#pragma unroll 4
    for (int it = 0; it < 32; it++) {
        int d = it * 2 + (tid >> 7);
        int t = tid & 127;
        size_t gidx = base + (size_t)d * HW + t;
        float x  = in[gidx];
        float q  = q_s[t * 68 + d];
        float dt = q - x;
        out_q[gidx] = x + dt;
        lsum = fmaf(dt, dt, lsum);
    }
#pragma unroll
    for (int off = 16; off > 0; off >>= 1)
        lsum += __shfl_xor_sync(0xffffffffu, lsum, off);
    if ((tid & 31) == 0) part[tid >> 5] = lsum;
    __syncthreads();
    if (tid == 0) {
        float s = 0.f;
#pragma unroll
        for (int i = 0; i < 8; i++) s += part[i];
        atomicAdd(&g_loss, s);
    }
}

// ---------------- kernel 6: finalize loss ----------------
__global__ void k_final(float* out) {
    out[0] = 0.25f * (g_loss * (1.0f / 16777216.0f));
}

// ---------------- launch ----------------
extern "C" void kernel_launch(void* const* d_in, const int* in_sizes, int n_in,
                              void* d_out, int out_size) {
    const float* in  = (const float*)d_in[0];   // (64,64,64,64) NCHW
    const float* w   = (const float*)d_in[1];   // (1024,64)
    const float* ecs = (const float*)d_in[2];   // (1024,)
    const float* ew  = (const float*)d_in[3];   // (1024,64)
    float* out      = (float*)d_out;            // [loss | quantized NCHW | idx]
    float* out_q    = out + 1;
    float* out_idx  = out + 1 + Q_ELEMS;

    const int ARG_SMEM = 65536 + 32768 + 512 + 1024;   // 99840 B

    k_prep<<<128, 256>>>(w);
    k_pack<<<64, 256>>>(w);
    cudaFuncSetAttribute(k_argmin, cudaFuncAttributeMaxDynamicSharedMemorySize, ARG_SMEM);
    k_argmin<<<N_TOK / 256, 256, ARG_SMEM>>>(in, out_idx);
    k_fix4<<<256, 256>>>(in, w, out_idx);
    k_sum<<<1, 1024>>>(ecs);
    k_updw<<<256, 256>>>(ecs, ew);
    k_gather<<<N_TOK / 128, 256>>>(in, out_q);
    k_final<<<1, 1>>>(out);
}

// round 11
// speedup vs baseline: 4.4231x; 1.0494x over previous
#include <cuda_runtime.h>
#include <cuda_fp16.h>
#include <math_constants.h>

#define N_TOK   262144
#define K_CODES 1024
#define D_DIM   64
#define HW      4096
#define CHW     262144
#define Q_ELEMS 16777216
#define GAP_T   5e-4f          // >= 2x worst-case fp16-split+fp32-accum noise bound
#define FIXCAP  65536

typedef unsigned int u32;

// ---------------- scratch (device globals; no allocation allowed) ----------------
__device__ uint4  g_Wpack[8 * 16 * 4 * 32];  // fragment-packed codebook {bh0,bh1,bl0,bl1}
__device__ float  g_wnh[K_CODES];            // 0.5*||w_k||^2 (fp32)
__device__ double g_wnh64[K_CODES];          // 0.5*||w_k||^2 (fp64, for exact repair)
__device__ float  g_counts[K_CODES];
__device__ float  g_dw[K_CODES * D_DIM];
__device__ float  g_neww[K_CODES * D_DIM];
__device__ float  g_loss;
__device__ float  g_n;
__device__ int    g_idx[N_TOK];
__device__ int    g_nfix;
__device__ int4   g_fixlist[FIXCAP];         // {token, k1, k2, tier2?}

// ---------------- helpers ----------------
__device__ __forceinline__ u32 smem_u32(const void* p) {
    u32 a;
    asm("{ .reg .u64 t; cvta.to.shared.u64 t, %1; cvt.u32.u64 %0, t; }" : "=r"(a) : "l"(p));
    return a;
}
#define CP_ASYNC16(dst, src) \
    asm volatile("cp.async.cg.shared.global [%0], [%1], 16;" :: "r"(dst), "l"(src))
#define CP_COMMIT() asm volatile("cp.async.commit_group;" ::: "memory")
#define CP_WAIT(n)  asm volatile("cp.async.wait_group %0;" :: "n"(n) : "memory")

__device__ __forceinline__ u32 h2_bits(__half2 h) {
    return *reinterpret_cast<u32*>(&h);
}
__device__ __forceinline__ void split_pair(float xa, float xb, u32& hi, u32& lo) {
    __half2 h = __floats2half2_rn(xa, xb);
    float2 hf = __half22float2(h);
    __half2 l = __floats2half2_rn(xa - hf.x, xb - hf.y);
    hi = h2_bits(h);
    lo = h2_bits(l);
}
__device__ __forceinline__ void mma16816(float* c, const u32* a, u32 b0, u32 b1) {
    asm("mma.sync.aligned.m16n8k16.row.col.f32.f16.f16.f32 "
        "{%0,%1,%2,%3}, {%4,%5,%6,%7}, {%8,%9}, {%0,%1,%2,%3};"
        : "+f"(c[0]), "+f"(c[1]), "+f"(c[2]), "+f"(c[3])
        : "r"(a[0]), "r"(a[1]), "r"(a[2]), "r"(a[3]), "r"(b0), "r"(b1));
}
__device__ __forceinline__ bool lt2(float s, int k, float s2, int k2) {
    return (s < s2) || (s == s2 && k < k2);
}
// top-3 insert: scores rs1<=rs2<=rs3, packed indices rk12 = (k2<<16)|k1
__device__ __forceinline__ void ins3(float s, int k,
                                     float& rs1, float& rs2, float& rs3, u32& rk12) {
    bool pa = s < rs1;
    bool pb = s < rs2;
    float nrs3 = pb ? rs2 : fminf(rs3, s);
    float nrs2 = pa ? rs1 : fminf(rs2, s);
    u32 ca = (rk12 << 16) | (u32)k;
    u32 cb = ((u32)k << 16) | (rk12 & 0xffffu);
    rk12 = pa ? ca : (pb ? cb : rk12);
    rs1 = fminf(rs1, s);
    rs2 = nrs2;
    rs3 = nrs3;
}

// ---------------- kernel 1: zero + coalesced norms (warp per code) ----------------
__global__ __launch_bounds__(256)
void k_prep(const float* __restrict__ w) {
    const int gt    = blockIdx.x * 256 + threadIdx.x;   // 0..32767
    const int kcode = gt >> 5;
    const int lane  = gt & 31;

    if (gt < K_CODES) g_counts[gt] = 0.f;
    g_dw[gt * 2]     = 0.f;
    g_dw[gt * 2 + 1] = 0.f;
    if (gt == 0) { g_loss = 0.f; g_nfix = 0; }

    float  v1 = w[kcode * 64 + lane];
    float  v2 = w[kcode * 64 + 32 + lane];
    double sd = (double)v1 * v1 + (double)v2 * v2;
#pragma unroll
    for (int off = 16; off > 0; off >>= 1)
        sd += __shfl_xor_sync(0xffffffffu, sd, off);
    if (lane == 0) {
        g_wnh64[kcode] = 0.5 * sd;
        g_wnh[kcode]   = (float)(0.5 * sd);
    }
}

// ---------------- kernel 2: pack codebook into mma B-fragment order --------------
// item -> (kt, nt, kst, lane); stores {bh0, bh1, bl0, bl1} for m16n8k16 col-major B.
// Layout matches the k_argmin smem tile byte-for-byte -> cp.async raw copy.
__global__ void k_pack(const float* __restrict__ w) {
    int item = blockIdx.x * 256 + threadIdx.x;    // 0..16383
    int lane = item & 31;
    int kst  = (item >> 5) & 3;
    int nt   = (item >> 7) & 15;
    int kt   = item >> 11;
    int n = kt * 128 + nt * 8 + (lane >> 2);
    int k = kst * 16 + 2 * (lane & 3);
    const float* wr = w + n * 64;
    u32 h0, l0, h1, l1;
    split_pair(wr[k],     wr[k + 1], h0, l0);
    split_pair(wr[k + 8], wr[k + 9], h1, l1);
    g_Wpack[item] = make_uint4(h0, h1, l0, l1);
}

// ---------------- kernel 3: tensor-core distances + top-3 + scatters + flags ------
// SMEM: [0,64K) = A32 (fp32 tile) during setup, then W double buffers (2 x 32K)
//       [64K, 68K) = all 1024 norms   [68K, 69K) = idx_s
#define SM_WN   65536
#define SM_IDX  69632
#define SM_TOT  70656

__global__ __launch_bounds__(256, 2)
void k_argmin(const float* __restrict__ in, float* __restrict__ out_idx_f) {
    extern __shared__ char smem[];
    const u32 sb = smem_u32(smem);
    float* A32   = (float*)smem;
    float* wn_s  = (float*)(smem + SM_WN);
    int*   idx_s = (int*)(smem + SM_IDX);

    const int tid  = threadIdx.x;
    const int warp = tid >> 5;
    const int lane = tid & 31;
    const int g    = lane >> 2;
    const int t    = lane & 3;
    const int token0 = blockIdx.x * 256;
    const int b   = token0 >> 12;
    const int hw0 = token0 & 4095;
    const float* Abase = in + (size_t)b * CHW + hw0;

    // Load A tile [64 d][256 tok] fp32 (coalesced) + all norms.
#pragma unroll
    for (int r = 0; r < 16; r++) {
        int m = r * 256 + tid;
        int d = m >> 6;
        int c = (m & 63) * 4;
        *(float4*)(A32 + d * 256 + c) = *(const float4*)(Abase + (size_t)d * HW + c);
    }
    ((float4*)wn_s)[tid] = ((const float4*)g_wnh)[tid];
    __syncthreads();

    // Build resident A fragments (hi/lo f16x2): 2 m-tiles x 4 k-steps x 4 regs.
    u32 Ah[2][4][4], Al[2][4][4];
#pragma unroll
    for (int mt = 0; mt < 2; mt++) {
        int r0 = warp * 32 + mt * 16 + g;
        int r1 = r0 + 8;
#pragma unroll
        for (int kst = 0; kst < 4; kst++) {
            int kb = kst * 16;
#pragma unroll
            for (int f = 0; f < 4; f++) {
                int row = (f & 1) ? r1 : r0;
                int kk  = kb + 2 * t + ((f >> 1) ? 8 : 0);
                split_pair(A32[kk * 256 + row], A32[(kk + 1) * 256 + row],
                           Ah[mt][kst][f], Al[mt][kst][f]);
            }
        }
    }
    __syncthreads();    // fragments built -> A32 region becomes W double buffers

    // cp.async prefetch of fragment-packed W tiles (raw copy, 8 x 16B per thread)
    auto prefetch = [&](int chunk, int buf) {
        u32 dst = sb + buf * 32768 + tid * 16;
        const uint4* src = g_Wpack + chunk * 2048 + tid;
#pragma unroll
        for (int r = 0; r < 8; r++)
            CP_ASYNC16(dst + r * 4096, (const void*)(src + r * 256));
    };

    float rs1[4], rs2[4], rs3[4];
    u32   rk12[4];
#pragma unroll
    for (int i = 0; i < 4; i++) {
        rs1[i] = CUDART_INF_F; rs2[i] = CUDART_INF_F; rs3[i] = CUDART_INF_F; rk12[i] = 0;
    }

    prefetch(0, 0);
    CP_COMMIT();

    for (int kt = 0; kt < 8; kt++) {
        if (kt < 7) {
            prefetch(kt + 1, (kt + 1) & 1);
            CP_COMMIT();
            CP_WAIT(1);                 // tile kt landed
        } else {
            CP_WAIT(0);
        }
        __syncthreads();
        const uint4* Wt4 = (const uint4*)(smem + (kt & 1) * 32768);

        for (int nt = 0; nt < 16; nt++) {
            float c0[4] = {0.f, 0.f, 0.f, 0.f};
            float c1[4] = {0.f, 0.f, 0.f, 0.f};
#pragma unroll
            for (int kst = 0; kst < 4; kst++) {
                uint4 bp = Wt4[(nt * 4 + kst) * 32 + lane];
                mma16816(c0, Ah[0][kst], bp.x, bp.y);   // ah*bh
                mma16816(c0, Al[0][kst], bp.x, bp.y);   // al*bh
                mma16816(c0, Ah[0][kst], bp.z, bp.w);   // ah*bl
                mma16816(c1, Ah[1][kst], bp.x, bp.y);
                mma16816(c1, Al[1][kst], bp.x, bp.y);
                mma16816(c1, Ah[1][kst], bp.z, bp.w);
            }
            float wa = wn_s[kt * 128 + nt * 8 + 2 * t];
            float wb = wn_s[kt * 128 + nt * 8 + 2 * t + 1];
            int   ka = kt * 128 + nt * 8 + 2 * t;
#pragma unroll
            for (int rr = 0; rr < 4; rr++) {
                const float* cc = (rr < 2) ? c0 : c1;
                float sa = wa - cc[(rr & 1) ? 2 : 0];
                float sb = wb - cc[(rr & 1) ? 3 : 1];
                ins3(sa, ka,     rs1[rr], rs2[rr], rs3[rr], rk12[rr]);
                ins3(sb, ka + 1, rs1[rr], rs2[rr], rs3[rr], rk12[rr]);
            }
        }
        __syncthreads();    // all warps done with this buffer before prefetch reuses it
    }

    // merge top-3 across the 4-lane column group
#pragma unroll
    for (int rr = 0; rr < 4; rr++) {
#pragma unroll
        for (int off = 1; off <= 2; off <<= 1) {
            float o1 = __shfl_xor_sync(0xffffffffu, rs1[rr], off, 4);
            float o2 = __shfl_xor_sync(0xffffffffu, rs2[rr], off, 4);
            float o3 = __shfl_xor_sync(0xffffffffu, rs3[rr], off, 4);
            u32   oj = __shfl_xor_sync(0xffffffffu, rk12[rr], off, 4);
            int j1 = oj & 0xffff, j2 = oj >> 16;
            float a1 = rs1[rr], a2 = rs2[rr], a3 = rs3[rr];
            int ak1 = rk12[rr] & 0xffff, ak2 = rk12[rr] >> 16;
            if (lt2(o1, j1, a1, ak1)) {
                rs1[rr] = o1;
                if (lt2(a1, ak1, o2, j2)) {
                    rk12[rr] = ((u32)ak1 << 16) | (u32)j1;
                    rs2[rr] = a1; rs3[rr] = fminf(a2, o2);
                } else {
                    rk12[rr] = ((u32)j2 << 16) | (u32)j1;
                    rs2[rr] = o2; rs3[rr] = fminf(a1, o3);
                }
            } else {
                if (lt2(o1, j1, a2, ak2)) {
                    rk12[rr] = ((u32)j1 << 16) | (u32)ak1;
                    rs2[rr] = o1; rs3[rr] = fminf(a2, o2);
                } else {
                    rs3[rr] = fminf(o1, a3);
                }
            }
        }
    }
    __syncthreads();
    if (t == 0) {
#pragma unroll
        for (int rr = 0; rr < 4; rr++) {
            int L = warp * 32 + (rr >> 1) * 16 + (rr & 1) * 8 + g;
            int k1 = rk12[rr] & 0xffff;
            idx_s[L] = k1;
            if (rs2[rr] - rs1[rr] < GAP_T) {
                int tier2 = (rs3[rr] - rs1[rr] < GAP_T) ? 1 : 0;
                int pos = atomicAdd(&g_nfix, 1);
                if (pos < FIXCAP)
                    g_fixlist[pos] = make_int4(token0 + L, k1, (int)(rk12[rr] >> 16), tier2);
            }
        }
    }
    __syncthreads();

    {
        int k = idx_s[tid];
        atomicAdd(&g_counts[k], 1.0f);
        g_idx[token0 + tid]     = k;
        out_idx_f[token0 + tid] = (float)k;
    }

    // dw scatter: re-read A from global (L2-warm), v4 vector reductions.
#pragma unroll
    for (int it = 0; it < 16; it++) {
        int m   = it * 256 + tid;
        int tkn = m & 255;
        int q   = m >> 8;
        float a0 = Abase[(size_t)(q * 4 + 0) * HW + tkn];
        float a1 = Abase[(size_t)(q * 4 + 1) * HW + tkn];
        float a2 = Abase[(size_t)(q * 4 + 2) * HW + tkn];
        float a3 = Abase[(size_t)(q * 4 + 3) * HW + tkn];
        float* p = g_dw + idx_s[tkn] * 64 + q * 4;
        asm volatile("red.global.add.v4.f32 [%0], {%1, %2, %3, %4};"
                     :: "l"(p), "f"(a0), "f"(a1), "f"(a2), "f"(a3) : "memory");
    }
}

// ---------------- kernel 3b: two-tier fp64 repair ----------------
__global__ __launch_bounds__(256)
void k_fix4(const float* __restrict__ in, const float* __restrict__ w,
            float* __restrict__ out_idx_f) {
    __shared__ float xs[8][64];
    int n = g_nfix; if (n > FIXCAP) n = FIXCAP;
    const int warp = threadIdx.x >> 5;
    const int lane = threadIdx.x & 31;
    for (int i = blockIdx.x * 8 + warp; i < n; i += gridDim.x * 8) {
        int4 e = g_fixlist[i];
        const int t = e.x;
        const float* x = in + (size_t)(t >> 12) * CHW + (t & 4095);
        float xv1f = x[(size_t)lane * HW];
        float xv2f = x[(size_t)(lane + 32) * HW];

        int bk;
        if (!e.w) {
            double xv1 = (double)xv1f, xv2 = (double)xv2f;
            double d1 = xv1 * (double)w[e.y * 64 + lane]
                      + xv2 * (double)w[e.y * 64 + 32 + lane];
            double d2 = xv1 * (double)w[e.z * 64 + lane]
                      + xv2 * (double)w[e.z * 64 + 32 + lane];
#pragma unroll
            for (int off = 16; off > 0; off >>= 1) {
                d1 += __shfl_xor_sync(0xffffffffu, d1, off);
                d2 += __shfl_xor_sync(0xffffffffu, d2, off);
            }
            double s1 = g_wnh64[e.y] - d1;
            double s2 = g_wnh64[e.z] - d2;
            bk = (s2 < s1 || (s2 == s1 && e.z < e.y)) ? e.z : e.y;
        } else {
            xs[warp][lane]      = xv1f;
            xs[warp][lane + 32] = xv2f;
            __syncwarp();
            double bd = CUDART_INF;
            bk = 0x7fffffff;
            for (int jj = 0; jj < 8; jj++) {
                int    c[4];
                double acc[4] = {0.0, 0.0, 0.0, 0.0};
#pragma unroll
                for (int u = 0; u < 4; u++) c[u] = (jj + u * 8) * 32 + lane;
#pragma unroll 4
                for (int q = 0; q < 16; q++) {
                    float4 wv[4];
#pragma unroll
                    for (int u = 0; u < 4; u++)
                        wv[u] = ((const float4*)(w + c[u] * 64))[q];
#pragma unroll
                    for (int r = 0; r < 4; r++) {
                        double xv = (double)xs[warp][q * 4 + r];
#pragma unroll
                        for (int u = 0; u < 4; u++)
                            acc[u] = fma(xv, (double)((&wv[u].x)[r]), acc[u]);
                    }
                }
#pragma unroll
                for (int u = 0; u < 4; u++) {
                    double s = g_wnh64[c[u]] - acc[u];
                    if (s < bd || (s == bd && c[u] < bk)) { bd = s; bk = c[u]; }
                }
            }
#pragma unroll
            for (int off = 16; off > 0; off >>= 1) {
                double od = __shfl_xor_sync(0xffffffffu, bd, off);
                int    ok = __shfl_xor_sync(0xffffffffu, bk, off);
                if (od < bd || (od == bd && ok < bk)) { bd = od; bk = ok; }
            }
            __syncwarp();
        }

        int old = e.y;
        if (bk != old) {
            if (lane == 0) {
                g_idx[t]     = bk;
                out_idx_f[t] = (float)bk;
                atomicAdd(&g_counts[old], -1.0f);
                atomicAdd(&g_counts[bk],   1.0f);
            }
            atomicAdd(&g_dw[old * 64 + lane],      -xv1f);
            atomicAdd(&g_dw[old * 64 + 32 + lane], -xv2f);
            atomicAdd(&g_dw[bk  * 64 + lane],       xv1f);
            atomicAdd(&g_dw[bk  * 64 + 32 + lane],  xv2f);
        }
    }
}

// ---------------- kernel 4a: n = sum(cs) ----------------
__global__ void k_sum(const float* __restrict__ ecs) {
    __shared__ float red[1024];
    int k = threadIdx.x;
    red[k] = ecs[k] * 0.99f + 0.01f * g_counts[k];
    __syncthreads();
    for (int s = 512; s > 0; s >>= 1) {
        if (k < s) red[k] += red[k + s];
        __syncthreads();
    }
    if (k == 0) g_n = red[0];
}

// ---------------- kernel 4b: EMA update, fully coalesced ----------------
__global__ __launch_bounds__(256)
void k_updw(const float* __restrict__ ecs, const float* __restrict__ ew) {
    int i = blockIdx.x * 256 + threadIdx.x;
    int k = i >> 6;
    float n  = g_n;
    float cs = ecs[k] * 0.99f + 0.01f * g_counts[k];
    float csn = (cs + 1e-5f) / (n + 1024.0f * 1e-5f) * n;
    float e = ew[i] * 0.99f + 0.01f * g_dw[i];
    g_neww[i] = e / csn;
}

// ---------------- kernel 5: gather + straight-through + loss partials -------------
__global__ __launch_bounds__(256)
void k_gather(const float* __restrict__ in, float* __restrict__ out_q) {
    __shared__ float q_s[128 * 68];
    __shared__ int   idx_s[128];
    __shared__ float part[8];
    const int tid = threadIdx.x;
    const int token0 = blockIdx.x * 128;
    const int b   = token0 >> 12;
    const int hw0 = token0 & 4095;

    if (tid < 128) idx_s[tid] = g_idx[token0 + tid];
    __syncthreads();

#pragma unroll
    for (int r = 0; r < 8; r++) {
        int m  = r * 256 + tid;
        int t  = m >> 4;
        int sg = (m & 15) * 4;
        float4 v = *(const float4*)(g_neww + idx_s[t] * 64 + sg);
        *(float4*)(q_s + t * 68 + sg) = v;
    }
    __syncthreads();

    const size_t base = (size_t)b * CHW + hw0;
    float lsum = 0.f;
#pragma unroll 4
    for (int it = 0; it < 32; it++) {
        int d = it * 2 + (tid >> 7);
        int t = tid & 127;
        size_t gidx = base + (size_t)d * HW + t;
        float x  = in[gidx];
        float q  = q_s[t * 68 + d];
        float dt = q - x;
        out_q[gidx] = x + dt;
        lsum = fmaf(dt, dt, lsum);
    }
#pragma unroll
    for (int off = 16; off > 0; off >>= 1)
        lsum += __shfl_xor_sync(0xffffffffu, lsum, off);
    if ((tid & 31) == 0) part[tid >> 5] = lsum;
    __syncthreads();
    if (tid == 0) {
        float s = 0.f;
#pragma unroll
        for (int i = 0; i < 8; i++) s += part[i];
        atomicAdd(&g_loss, s);
    }
}

// ---------------- kernel 6: finalize loss ----------------
__global__ void k_final(float* out) {
    out[0] = 0.25f * (g_loss * (1.0f / 16777216.0f));
}

// ---------------- launch ----------------
extern "C" void kernel_launch(void* const* d_in, const int* in_sizes, int n_in,
                              void* d_out, int out_size) {
    const float* in  = (const float*)d_in[0];   // (64,64,64,64) NCHW
    const float* w   = (const float*)d_in[1];   // (1024,64)
    const float* ecs = (const float*)d_in[2];   // (1024,)
    const float* ew  = (const float*)d_in[3];   // (1024,64)
    float* out      = (float*)d_out;            // [loss | quantized NCHW | idx]
    float* out_q    = out + 1;
    float* out_idx  = out + 1 + Q_ELEMS;

    k_prep<<<128, 256>>>(w);
    k_pack<<<64, 256>>>(w);
    cudaFuncSetAttribute(k_argmin, cudaFuncAttributeMaxDynamicSharedMemorySize, SM_TOT);
    k_argmin<<<N_TOK / 256, 256, SM_TOT>>>(in, out_idx);
    k_fix4<<<256, 256>>>(in, w, out_idx);
    k_sum<<<1, 1024>>>(ecs);
    k_updw<<<256, 256>>>(ecs, ew);
    k_gather<<<N_TOK / 128, 256>>>(in, out_q);
    k_final<<<1, 1>>>(out);
}